// round 8
// baseline (speedup 1.0000x reference)
#include <cuda_runtime.h>
#include <cuda_bf16.h>
#include <math.h>

#define NPN   30000
#define EPE   480000
#define NLIG  48
#define ELIG  144
#define TSTEP 96
#define N1    49
#define DD    256
#define NEGC  (-1.0e9f)

// ---------------- device scratch (static; no allocations) ----------------
__device__ int   g_deg[NPN];
__device__ float g_dinv[NPN];
__device__ float g_y[NPN * 15];
__device__ float g_c[NPN];
__device__ float g_t[DD];
__device__ float g_Apok[4];
__device__ float g_CONST[4];     // H_t lab part + H_init + bh
__device__ float g_labg[N1];     // Wg[780 + lab_i]
__device__ int   g_lab49[N1];
__device__ float g_Wd2P[DD * 13];
__device__ float g_bd2P[13];
// sim outputs
__device__ int   g_nedges;
__device__ int   g_dsrc[193], g_ddst[193];
__device__ int   g_su[TSTEP], g_sv[TSTEP], g_sb[TSTEP], g_sstate[TSTEP];
__device__ unsigned char g_sact[TSTEP], g_sdo[TSTEP];
__device__ float g_stime[TSTEP];
__device__ unsigned long long g_smask[TSTEP];
__device__ float g_se[TSTEP * 4];
// per-state projected GCN outputs
__device__ float g_zP[97 * N1 * 13];
__device__ float g_mzP[97 * 13];

// ---------------- pocket GCN (mean only) ----------------
__global__ void k_zero() {
    int i = blockIdx.x * blockDim.x + threadIdx.x;
    if (i < NPN) g_deg[i] = 0;
}

__global__ void k_deg(const int* __restrict__ dst) {
    int e = blockIdx.x * blockDim.x + threadIdx.x;
    if (e < EPE) atomicAdd(&g_deg[dst[e]], 1);
}

__global__ void k_dinv(const float* __restrict__ xp) {
    int i = blockIdx.x * blockDim.x + threadIdx.x;
    if (i < NPN) {
        float di = rsqrtf((float)(g_deg[i] + 1));
        g_dinv[i] = di;
        float w = di * di;
        g_c[i] = w;                       // self-loop contribution to c_s
        const float* xr = xp + i * 15;
        float* yr = g_y + i * 15;
#pragma unroll
        for (int k = 0; k < 15; k++) yr[k] = xr[k] * w;  // self-loop into y
    }
    if (i < DD) g_t[i] = 0.f;
}

__global__ void k_edge(const float* __restrict__ xp, const int* __restrict__ src,
                       const int* __restrict__ dst) {
    int e = blockIdx.x * blockDim.x + threadIdx.x;
    if (e >= EPE) return;
    int s = src[e], d = dst[e];
    float nm = g_dinv[s] * g_dinv[d];
    const float* xs = xp + s * 15;
    float* yd = g_y + d * 15;
#pragma unroll
    for (int k = 0; k < 15; k++) atomicAdd(yd + k, xs[k] * nm);
    atomicAdd(&g_c[s], nm);
}

// t[d] = sum_s c_s * relu(y[s]@Wp1[:,d] + bp1[d])
__global__ void k_hred(const float* __restrict__ Wp1, const float* __restrict__ bp1) {
    __shared__ float sy[64 * 15];
    __shared__ float sc[64];
    int n0 = blockIdx.x * 64;
    int nn = min(64, NPN - n0);
    int tid = threadIdx.x;
    float wc[15];
#pragma unroll
    for (int k = 0; k < 15; k++) wc[k] = Wp1[k * DD + tid];
    float b = bp1[tid];
    for (int idx = tid; idx < nn * 15; idx += 256) sy[idx] = g_y[n0 * 15 + idx];
    if (tid < nn) sc[tid] = g_c[n0 + tid];
    __syncthreads();
    float acc = 0.f;
    for (int j = 0; j < nn; j++) {
        float v = b;
#pragma unroll
        for (int k = 0; k < 15; k++) v += sy[j * 15 + k] * wc[k];
        v = fmaxf(v, 0.f);
        acc += sc[j] * v;
    }
    atomicAdd(&g_t[tid], acc);
}

// z_pocket = bp2 + (1/N) t@Wp2 ; Apok_j = z_pocket . Wh[1:257, j]
__global__ void k_zp(const float* __restrict__ Wp2, const float* __restrict__ bp2,
                     const float* __restrict__ Wh) {
    __shared__ float st[DD];
    __shared__ float szp[DD];
    int tid = threadIdx.x;
    st[tid] = g_t[tid];
    __syncthreads();
    float acc = 0.f;
    for (int k = 0; k < DD; k++) acc += st[k] * Wp2[k * DD + tid];
    szp[tid] = bp2[tid] + acc * (1.f / (float)NPN);
    __syncthreads();
    int w = tid >> 5, lane = tid & 31;
    if (w < 4) {
        float p = 0.f;
        for (int d = lane; d < DD; d += 32) p += szp[d] * Wh[(1 + d) * 4 + w];
        for (int o = 16; o; o >>= 1) p += __shfl_xor_sync(0xffffffffu, p, o);
        if (lane == 0) g_Apok[w] = p;
    }
}

// ---------------- ligand GCN mean + constants ----------------
__global__ void k_ligand(const float* __restrict__ xg, const int* __restrict__ xlab,
                         const int* __restrict__ srcl, const int* __restrict__ dstl,
                         const float* __restrict__ Wl1, const float* __restrict__ bl1,
                         const float* __restrict__ Wl2, const float* __restrict__ bl2,
                         const float* __restrict__ Wg, const float* __restrict__ Wh,
                         const float* __restrict__ bh) {
    __shared__ float xl[NLIG * 15];
    __shared__ float yl[NLIG * 15];
    __shared__ float dinv[NLIG], cl[NLIG], tl[DD], mz[DD];
    __shared__ int deg[NLIG], lab[NLIG];
    int tid = threadIdx.x;
    for (int i = tid; i < NLIG * 15; i += 256) xl[i] = 0.f;
    if (tid < NLIG) { deg[tid] = 0; lab[tid] = xlab[tid]; }
    __syncthreads();
    if (tid < NLIG) {
        for (int k = 0; k < 4; k++) xl[tid * 15 + k] = xg[tid * 4 + k];
        xl[tid * 15 + 4 + lab[tid]] = 1.f;
    }
    __syncthreads();
    if (tid < ELIG) atomicAdd(&deg[dstl[tid]], 1);
    __syncthreads();
    if (tid < NLIG) {
        float di = rsqrtf((float)(deg[tid] + 1));
        dinv[tid] = di;
        cl[tid] = di * di;
        for (int k = 0; k < 15; k++) yl[tid * 15 + k] = xl[tid * 15 + k] * di * di;
    }
    __syncthreads();
    if (tid < ELIG) {
        int s = srcl[tid], d = dstl[tid];
        float nm = dinv[s] * dinv[d];
        for (int k = 0; k < 15; k++) atomicAdd(&yl[d * 15 + k], xl[s * 15 + k] * nm);
        atomicAdd(&cl[s], nm);
    }
    __syncthreads();
    {   // tl[d] = sum_s c_s relu(bl1[d] + y[s]@Wl1[:,d])
        float acc = 0.f;
        float b = bl1[tid];
        for (int s = 0; s < NLIG; s++) {
            float v = b;
#pragma unroll
            for (int k = 0; k < 15; k++) v += yl[s * 15 + k] * Wl1[k * DD + tid];
            acc += cl[s] * fmaxf(v, 0.f);
        }
        tl[tid] = acc;
    }
    __syncthreads();
    {   // mean(z_l)[d]
        float acc = 0.f;
        for (int k = 0; k < DD; k++) acc += tl[k] * Wl2[k * DD + tid];
        mz[tid] = bl2[tid] + acc * (1.f / 48.f);
    }
    __syncthreads();
    if (tid < N1) {
        int l = (tid < NLIG) ? lab[tid] : 10;
        g_lab49[tid] = l;
        g_labg[tid] = Wg[780 + l];
    }
    int w = tid >> 5, lane = tid & 31;
    if (w < 4) {
        int j = w;
        float p = 0.f;
        for (int d = lane; d < DD; d += 32) p += mz[d] * Wh[(1058 + d) * 4 + j];
        for (int n = lane; n < N1; n += 32) {
            int l = (n < NLIG) ? lab[n] : 10;
            p += (1.f / 49.f) * Wh[(1047 + l) * 4 + j];
        }
        for (int n = lane; n < NLIG; n += 32)
            p += (1.f / 48.f) * Wh[(1314 + lab[n]) * 4 + j];
        for (int o = 16; o; o >>= 1) p += __shfl_xor_sync(0xffffffffu, p, o);
        if (lane == 0) g_CONST[j] = p + bh[j];
    }
}

// ---------------- Wd2 @ P (P gathers Wg/Wh slices) ----------------
__global__ void k_wd2p(const float* __restrict__ Wd2, const float* __restrict__ bd2,
                       const float* __restrict__ Wg, const float* __restrict__ Wh) {
    int c = blockIdx.x;      // 0..12
    int r = threadIdx.x;     // 0..255
    float acc = 0.f, accb = 0.f;
    for (int kk = 0; kk < DD; kk++) {
        float p;
        if (c == 0)       p = Wg[524 + kk];
        else if (c < 5)   p = Wh[(257 + kk) * 4 + (c - 1)];
        else if (c < 9)   p = Wh[(524 + kk) * 4 + (c - 5)];
        else              p = Wh[(791 + kk) * 4 + (c - 9)];
        acc += Wd2[r * DD + kk] * p;
        if (r == 0) accb += bd2[kk] * p;
    }
    g_Wd2P[r * 13 + c] = acc;
    if (r == 0) g_bd2P[c] = accb;
}

// ---------------- serial teacher-forced control simulation ----------------
__global__ void k_sim(const int* __restrict__ bfs_index, const int* __restrict__ bfs_bond) {
    if (threadIdx.x != 0) return;
    const float VALV[11] = {4.f,1.f,3.f,1.f,2.f,1.f,5.f,1.f,6.f,1.f,1000.f};
    const float BV[4] = {1.f,2.f,3.f,1.5f};
    const unsigned long long ALL49 = (1ull << 49) - 1ull;
    float val[N1];
    unsigned long long adj[N1];
    unsigned long long lowm = 0ull, closedm = 0ull;
    int Q[97];
    for (int i = 0; i < N1; i++) {
        val[i] = VALV[g_lab49[i]];
        adj[i] = 0ull;
        if (val[i] < 1.f) lowm |= (1ull << i);
    }
    int head = 0, tail = 1;
    Q[0] = bfs_index[0];
    int ne = 0;
    float tf = 0.f;
    g_dsrc[0] = bfs_index[0];
    g_ddst[0] = bfs_index[1];
    for (int t = 0; t < TSTEP; t++) {
        int v = bfs_index[t * 2 + 1], b = bfs_bond[t];
        int active = (tail > head) ? 1 : 0;
        g_sact[t] = (unsigned char)active;
        g_sv[t] = v; g_sb[t] = b; g_sstate[t] = ne; g_stime[t] = tf;
        if (!active) {
            g_sdo[t] = 0; g_su[t] = 0; g_smask[t] = 0ull;
            g_se[t*4] = g_se[t*4+1] = g_se[t*4+2] = g_se[t*4+3] = 0.f;
            continue;
        }
        int u = Q[head];
        g_su[t] = u;
        bool ulow = ((lowm >> u) & 1ull) != 0ull;
        unsigned long long base = lowm | closedm | adj[u] | (1ull << u);
        unsigned long long mask = ulow ? ALL49 : base;
        mask &= ~((1ull << v) | (1ull << 48));
        g_smask[t] = mask;
        bool mnouv = ulow || (((base >> v) & 1ull) != 0ull);
        int doe = (v != 48);
        g_sdo[t] = (unsigned char)doe;
        if (doe) {
            float mv = fminf(val[u], val[v]);
            float e0 = 0.f, e1 = 0.f, e2 = 0.f, e3 = 0.f;
            if (mv <= 2.f) { e2 = NEGC; }
            if (mv <= 1.f) { e0 = 0.f; e1 = NEGC; e2 = NEGC; e3 = 0.f; }
            if (mv <= 0.f) { e0 = NEGC; e1 = NEGC; e2 = NEGC; e3 = NEGC; }
            if (mnouv)     { e0 = NEGC; e1 = NEGC; e2 = NEGC; e3 = NEGC; }
            if (b == 0) e0 = 0.f; else if (b == 1) e1 = 0.f;
            else if (b == 2) e2 = 0.f; else e3 = 0.f;
            g_se[t*4] = e0; g_se[t*4+1] = e1; g_se[t*4+2] = e2; g_se[t*4+3] = e3;
            if (tail < 97) Q[tail] = v;
            tail++;
            ne++;
            g_dsrc[2*ne-1] = u; g_ddst[2*ne-1] = v;
            g_dsrc[2*ne]   = v; g_ddst[2*ne]   = u;
            float dec = BV[b];
            val[u] -= dec;
            val[v] -= dec;
            if (val[u] < 1.f) lowm |= (1ull << u); else lowm &= ~(1ull << u);
            if (val[v] < 1.f) lowm |= (1ull << v); else lowm &= ~(1ull << v);
            adj[u] |= (1ull << v);
            adj[v] |= (1ull << u);
            tf += 1.f;
        } else {
            closedm |= (1ull << u);
            head++;
            g_se[t*4] = g_se[t*4+1] = g_se[t*4+2] = g_se[t*4+3] = 0.f;
        }
    }
    g_nedges = ne;
}

// ---------------- per-state inner GCN, projected to 13 dims ----------------
#define SMEM_STATES_FLOATS (N1*DD + 637 + 637 + 192 + N1 + N1 + 192 + 192 + N1)
#define SMEM_STATES_BYTES  (SMEM_STATES_FLOATS * 4)

__global__ void k_states(const float* __restrict__ Wd1, const float* __restrict__ bd1) {
    extern __shared__ float sm[];
    float* sh    = sm;                    // 49*256
    float* sg    = sh + N1 * DD;          // 637
    float* sz    = sg + 637;              // 637
    float* wE    = sz + 637;              // 192
    float* sdinv = wE + 192;              // 49
    int* slab = (int*)(sdinv + N1);       // 49
    int* ses  = slab + N1;                // 192
    int* sed  = ses + 192;                // 192
    int* sdeg = sed + 192;                // 49
    int k = blockIdx.x;
    int K = g_nedges;
    if (k > K) return;
    int tid = threadIdx.x;
    int off = (k == 0) ? 0 : 1;
    int cnt = (k == 0) ? 1 : 2 * k;
    if (tid < N1) { slab[tid] = g_lab49[tid]; sdeg[tid] = 0; }
    if (tid < cnt) { ses[tid] = g_dsrc[off + tid]; sed[tid] = g_ddst[off + tid]; }
    __syncthreads();
    if (tid < cnt) atomicAdd(&sdeg[sed[tid]], 1);
    __syncthreads();
    if (tid < N1) sdinv[tid] = rsqrtf((float)(sdeg[tid] + 1));
    __syncthreads();
    if (tid < cnt) wE[tid] = sdinv[ses[tid]] * sdinv[sed[tid]];
    __syncthreads();
    // layer 1 : h = relu(bd1 + self + scatter(Wd1[lab[src]] * norm))
    {
        int d = tid;
        float bd = bd1[d];
        for (int i = 0; i < N1; i++)
            sh[i * DD + d] = bd + Wd1[slab[i] * DD + d] * sdinv[i] * sdinv[i];
        for (int e = 0; e < cnt; e++)
            sh[sed[e] * DD + d] += Wd1[slab[ses[e]] * DD + d] * wE[e];
        for (int i = 0; i < N1; i++)
            sh[i * DD + d] = fmaxf(sh[i * DD + d], 0.f);
    }
    __syncthreads();
    // layer 2 projected: sg[i,c] = h[i] @ Wd2P[:,c]
    {
        int w = tid >> 5, lane = tid & 31;
        for (int t = w; t < 637; t += 8) {
            int i = t / 13, c = t - i * 13;
            float p = 0.f;
            for (int d = lane; d < DD; d += 32)
                p += sh[i * DD + d] * g_Wd2P[d * 13 + c];
            for (int o = 16; o; o >>= 1) p += __shfl_xor_sync(0xffffffffu, p, o);
            if (lane == 0) sg[t] = p;
        }
    }
    __syncthreads();
    if (tid < 637) {
        int i = tid / 13, c = tid - i * 13;
        sz[tid] = g_bd2P[c] + sg[tid] * sdinv[i] * sdinv[i];
    }
    __syncthreads();
    if (tid < 13) {   // serial scatter over edges (13 lanes, one per projection)
        int c = tid;
        for (int e = 0; e < cnt; e++)
            sz[sed[e] * 13 + c] += sg[ses[e] * 13 + c] * wE[e];
    }
    __syncthreads();
    if (tid < 637) g_zP[k * N1 * 13 + tid] = sz[tid];
    if (tid < 13) {
        float s = 0.f;
        for (int i = 0; i < N1; i++) s += sz[i * 13 + tid];
        g_mzP[k * 13 + tid] = s * (1.f / 49.f);
    }
}

// ---------------- final assembly of logp ----------------
__global__ void k_assemble(const float* __restrict__ Wh, float* __restrict__ out) {
    __shared__ float wsum[8];
    int tid = threadIdx.x, w = tid >> 5, lane = tid & 31;
    float acc = 0.f;
    for (int t = w; t < TSTEP; t += 8) {
        if (!g_sact[t]) continue;
        int st = g_sstate[t], v = g_sv[t], u = g_su[t], b = g_sb[t];
        unsigned long long mask = g_smask[t];
        const float* zPs = g_zP + st * N1 * 13;
        // glog softmax over 49 of zP[:,0] + labg + m
        int i0 = lane, i1 = lane + 32;
        float s0 = zPs[i0 * 13] + g_labg[i0] + (((mask >> i0) & 1ull) ? NEGC : 0.f);
        float s1 = (i1 < N1)
                 ? (zPs[i1 * 13] + g_labg[i1] + (((mask >> i1) & 1ull) ? NEGC : 0.f))
                 : -3.0e38f;
        float mx = fmaxf(s0, s1);
        for (int o = 16; o; o >>= 1) mx = fmaxf(mx, __shfl_xor_sync(0xffffffffu, mx, o));
        float se = expf(s0 - mx) + ((i1 < N1) ? expf(s1 - mx) : 0.f);
        for (int o = 16; o; o >>= 1) se += __shfl_xor_sync(0xffffffffu, se, o);
        float sgv = zPs[v * 13] + g_labg[v];     // m[v] == 0 always
        acc += sgv - (mx + logf(se));
        if (g_sdo[t]) {
            int j = lane & 3;
            int lu = g_lab49[u], lv = g_lab49[v];
            float h = g_stime[t] * Wh[j] + g_Apok[j]
                    + zPs[u * 13 + 1 + j] + Wh[(513 + lu) * 4 + j]
                    + zPs[v * 13 + 5 + j] + Wh[(780 + lv) * 4 + j]
                    + g_mzP[st * 13 + 9 + j] + g_CONST[j] + g_se[t * 4 + j];
            float m4 = h;
            m4 = fmaxf(m4, __shfl_xor_sync(0xffffffffu, m4, 1, 4));
            m4 = fmaxf(m4, __shfl_xor_sync(0xffffffffu, m4, 2, 4));
            float s4 = expf(h - m4);
            s4 += __shfl_xor_sync(0xffffffffu, s4, 1, 4);
            s4 += __shfl_xor_sync(0xffffffffu, s4, 2, 4);
            float hb = __shfl_sync(0xffffffffu, h, b, 4);
            acc += hb - (m4 + logf(s4));
        }
    }
    if (lane == 0) wsum[w] = acc;
    __syncthreads();
    if (tid == 0) {
        float s = 0.f;
        for (int i = 0; i < 8; i++) s += wsum[i];
        out[0] = s;
    }
}

// ---------------- launcher ----------------
extern "C" void kernel_launch(void* const* d_in, const int* in_sizes, int n_in,
                              void* d_out, int out_size) {
    (void)in_sizes; (void)n_in; (void)out_size;
    const float* x_p   = (const float*)d_in[0];
    const int*   src_p = (const int*)d_in[1];
    const int*   dst_p = (const int*)d_in[2];
    const float* x_lg  = (const float*)d_in[3];
    const int*   x_ll  = (const int*)d_in[4];
    const int*   src_l = (const int*)d_in[5];
    const int*   dst_l = (const int*)d_in[6];
    const int*   bfsi  = (const int*)d_in[7];
    const int*   bfsb  = (const int*)d_in[8];
    const float* Wp1 = (const float*)d_in[9];
    const float* bp1 = (const float*)d_in[10];
    const float* Wp2 = (const float*)d_in[11];
    const float* bp2 = (const float*)d_in[12];
    const float* Wl1 = (const float*)d_in[13];
    const float* bl1 = (const float*)d_in[14];
    const float* Wl2 = (const float*)d_in[15];
    const float* bl2 = (const float*)d_in[16];
    const float* Wd1 = (const float*)d_in[17];
    const float* bd1 = (const float*)d_in[18];
    const float* Wd2 = (const float*)d_in[19];
    const float* bd2 = (const float*)d_in[20];
    // d_in[21] = Wf, d_in[22] = bf : dead code (logp reset by carry0)
    const float* Wg  = (const float*)d_in[23];
    // d_in[24] = bg : cancels under softmax shift-invariance
    const float* Wh  = (const float*)d_in[25];
    const float* bh  = (const float*)d_in[26];
    float* out = (float*)d_out;

    cudaFuncSetAttribute(k_states, cudaFuncAttributeMaxDynamicSharedMemorySize,
                         SMEM_STATES_BYTES);

    k_zero<<<(NPN + 255) / 256, 256>>>();
    k_deg<<<(EPE + 255) / 256, 256>>>(dst_p);
    k_dinv<<<(NPN + 255) / 256, 256>>>(x_p);
    k_edge<<<(EPE + 255) / 256, 256>>>(x_p, src_p, dst_p);
    k_hred<<<(NPN + 63) / 64, 256>>>(Wp1, bp1);
    k_zp<<<1, 256>>>(Wp2, bp2, Wh);
    k_ligand<<<1, 256>>>(x_lg, x_ll, src_l, dst_l, Wl1, bl1, Wl2, bl2, Wg, Wh, bh);
    k_wd2p<<<13, 256>>>(Wd2, bd2, Wg, Wh);
    k_sim<<<1, 32>>>(bfsi, bfsb);
    k_states<<<97, 256, SMEM_STATES_BYTES>>>(Wd1, bd1);
    k_assemble<<<1, 256>>>(Wh, out);
}

// round 11
// speedup vs baseline: 1.2863x; 1.2863x over previous
#include <cuda_runtime.h>
#include <cuda_bf16.h>
#include <math.h>

#define NPN   30000
#define EPE   480000
#define NLIG  48
#define ELIG  144
#define TSTEP 96
#define N1    49
#define DD    256
#define NEGC  (-1.0e9f)

// ---------------- device scratch (static; no allocations) ----------------
__device__ int   g_deg[NPN];
__device__ float g_dinv[NPN];
__device__ __align__(16) float g_y[NPN * 16];   // padded to 16 floats/row
__device__ float g_c[NPN];
__device__ float g_t[DD];
__device__ float g_Apok[4];
__device__ float g_CONST[4];     // H_t lab part + H_init + bh
__device__ float g_labg[N1];     // Wg[780 + lab_i]
__device__ int   g_lab49[N1];
__device__ float g_Wd2P[DD * 13];
__device__ float g_bd2P[13];
// sim outputs
__device__ int   g_nedges;
__device__ int   g_dsrc[193], g_ddst[193];
__device__ int   g_su[TSTEP], g_sv[TSTEP], g_sb[TSTEP], g_sstate[TSTEP];
__device__ unsigned char g_sact[TSTEP], g_sdo[TSTEP];
__device__ float g_stime[TSTEP];
__device__ unsigned long long g_smask[TSTEP];
__device__ float g_se[TSTEP * 4];
// per-state projected GCN outputs
__device__ float g_zP[97 * N1 * 13];
__device__ float g_mzP[97 * 13];

// ---------------- pocket GCN (mean only) ----------------
__global__ void k_zero() {
    int i = blockIdx.x * blockDim.x + threadIdx.x;
    if (i < NPN) g_deg[i] = 0;
    if (i < DD) g_t[i] = 0.f;
}

__global__ void k_deg(const int* __restrict__ dst) {
    int e = blockIdx.x * blockDim.x + threadIdx.x;
    if (e < EPE) atomicAdd(&g_deg[dst[e]], 1);
}

__global__ void k_dinv(const float* __restrict__ xp) {
    int i = blockIdx.x * blockDim.x + threadIdx.x;
    if (i >= NPN) return;
    float di = rsqrtf((float)(g_deg[i] + 1));
    g_dinv[i] = di;
    float w = di * di;
    g_c[i] = w;                       // self-loop contribution to c_s
    const float* xr = xp + i * 15;
    float v[16];
#pragma unroll
    for (int k = 0; k < 15; k++) v[k] = xr[k] * w;   // self-loop into y
    v[15] = 0.f;
    float4* yr = (float4*)(g_y + i * 16);
    yr[0] = make_float4(v[0], v[1], v[2], v[3]);
    yr[1] = make_float4(v[4], v[5], v[6], v[7]);
    yr[2] = make_float4(v[8], v[9], v[10], v[11]);
    yr[3] = make_float4(v[12], v[13], v[14], v[15]);
}

// scalar atomics (proven path)
__global__ void k_edge(const float* __restrict__ xp, const int* __restrict__ src,
                       const int* __restrict__ dst) {
    int e = blockIdx.x * blockDim.x + threadIdx.x;
    if (e >= EPE) return;
    int s = src[e], d = dst[e];
    float nm = g_dinv[s] * g_dinv[d];
    const float* xs = xp + s * 15;
    float* yd = g_y + d * 16;
#pragma unroll
    for (int k = 0; k < 15; k++) atomicAdd(yd + k, xs[k] * nm);
    atomicAdd(&g_c[s], nm);
}

// t[d] = sum_s c_s * relu(y[s]@Wp1[:,d] + bp1[d])
__global__ void k_hred(const float* __restrict__ Wp1, const float* __restrict__ bp1) {
    __shared__ float4 sy4[128 * 4];
    __shared__ float sc[128];
    int n0 = blockIdx.x * 128;
    int nn = min(128, NPN - n0);
    int tid = threadIdx.x;
    float wc[15];
#pragma unroll
    for (int k = 0; k < 15; k++) wc[k] = Wp1[k * DD + tid];
    float b = bp1[tid];
    for (int idx = tid; idx < nn * 4; idx += 256)
        sy4[idx] = ((const float4*)g_y)[n0 * 4 + idx];
    if (tid < nn) sc[tid] = g_c[n0 + tid];
    __syncthreads();
    const float* sy = (const float*)sy4;
    float acc = 0.f;
    for (int j = 0; j < nn; j++) {
        float v = b;
#pragma unroll
        for (int k = 0; k < 15; k++) v += sy[j * 16 + k] * wc[k];
        acc += sc[j] * fmaxf(v, 0.f);
    }
    atomicAdd(&g_t[tid], acc);
}

// ---------------- fused small kernels: zp / ligand / wd2p / sim ----------------
__global__ void k_small(const float* __restrict__ Wp2, const float* __restrict__ bp2,
                        const float* __restrict__ Wh,
                        const float* __restrict__ xg, const int* __restrict__ xlab,
                        const int* __restrict__ srcl, const int* __restrict__ dstl,
                        const float* __restrict__ Wl1, const float* __restrict__ bl1,
                        const float* __restrict__ Wl2, const float* __restrict__ bl2,
                        const float* __restrict__ Wg, const float* __restrict__ bh,
                        const float* __restrict__ Wd2, const float* __restrict__ bd2,
                        const int* __restrict__ bfsi, const int* __restrict__ bfsb) {
    int blk = blockIdx.x;
    int tid = threadIdx.x;
    if (blk == 0) {
        // z_pocket = bp2 + (1/N) t@Wp2 ; Apok_j = z_pocket . Wh[1:257, j]
        __shared__ float st[DD];
        __shared__ float szp[DD];
        st[tid] = g_t[tid];
        __syncthreads();
        float acc = 0.f;
        for (int k = 0; k < DD; k++) acc += st[k] * Wp2[k * DD + tid];
        szp[tid] = bp2[tid] + acc * (1.f / (float)NPN);
        __syncthreads();
        int w = tid >> 5, lane = tid & 31;
        if (w < 4) {
            float p = 0.f;
            for (int d = lane; d < DD; d += 32) p += szp[d] * Wh[(1 + d) * 4 + w];
            for (int o = 16; o; o >>= 1) p += __shfl_xor_sync(0xffffffffu, p, o);
            if (lane == 0) g_Apok[w] = p;
        }
    } else if (blk == 1) {
        // ligand GCN mean + constants
        __shared__ float xl[NLIG * 15];
        __shared__ float yl[NLIG * 15];
        __shared__ float dinv[NLIG], cl[NLIG], tl[DD], mz[DD];
        __shared__ int deg[NLIG], lab[NLIG];
        for (int i = tid; i < NLIG * 15; i += 256) xl[i] = 0.f;
        if (tid < NLIG) { deg[tid] = 0; lab[tid] = xlab[tid]; }
        __syncthreads();
        if (tid < NLIG) {
            for (int k = 0; k < 4; k++) xl[tid * 15 + k] = xg[tid * 4 + k];
            xl[tid * 15 + 4 + lab[tid]] = 1.f;
        }
        __syncthreads();
        if (tid < ELIG) atomicAdd(&deg[dstl[tid]], 1);
        __syncthreads();
        if (tid < NLIG) {
            float di = rsqrtf((float)(deg[tid] + 1));
            dinv[tid] = di;
            cl[tid] = di * di;
            for (int k = 0; k < 15; k++) yl[tid * 15 + k] = xl[tid * 15 + k] * di * di;
        }
        __syncthreads();
        if (tid < ELIG) {
            int s = srcl[tid], d = dstl[tid];
            float nm = dinv[s] * dinv[d];
            for (int k = 0; k < 15; k++) atomicAdd(&yl[d * 15 + k], xl[s * 15 + k] * nm);
            atomicAdd(&cl[s], nm);
        }
        __syncthreads();
        {
            float acc = 0.f;
            float b = bl1[tid];
            for (int s = 0; s < NLIG; s++) {
                float v = b;
#pragma unroll
                for (int k = 0; k < 15; k++) v += yl[s * 15 + k] * Wl1[k * DD + tid];
                acc += cl[s] * fmaxf(v, 0.f);
            }
            tl[tid] = acc;
        }
        __syncthreads();
        {
            float acc = 0.f;
            for (int k = 0; k < DD; k++) acc += tl[k] * Wl2[k * DD + tid];
            mz[tid] = bl2[tid] + acc * (1.f / 48.f);
        }
        __syncthreads();
        if (tid < N1) {
            int l = (tid < NLIG) ? lab[tid] : 10;
            g_lab49[tid] = l;
            g_labg[tid] = Wg[780 + l];
        }
        int w = tid >> 5, lane = tid & 31;
        if (w < 4) {
            int j = w;
            float p = 0.f;
            for (int d = lane; d < DD; d += 32) p += mz[d] * Wh[(1058 + d) * 4 + j];
            for (int n = lane; n < N1; n += 32) {
                int l = (n < NLIG) ? lab[n] : 10;
                p += (1.f / 49.f) * Wh[(1047 + l) * 4 + j];
            }
            for (int n = lane; n < NLIG; n += 32)
                p += (1.f / 48.f) * Wh[(1314 + lab[n]) * 4 + j];
            for (int o = 16; o; o >>= 1) p += __shfl_xor_sync(0xffffffffu, p, o);
            if (lane == 0) g_CONST[j] = p + bh[j];
        }
    } else if (blk < 15) {
        // Wd2 @ P column c = blk-2
        int c = blk - 2;
        int r = tid;
        float acc = 0.f, accb = 0.f;
        for (int kk = 0; kk < DD; kk++) {
            float p;
            if (c == 0)       p = Wg[524 + kk];
            else if (c < 5)   p = Wh[(257 + kk) * 4 + (c - 1)];
            else if (c < 9)   p = Wh[(524 + kk) * 4 + (c - 5)];
            else              p = Wh[(791 + kk) * 4 + (c - 9)];
            acc += Wd2[r * DD + kk] * p;
            if (r == 0) accb += bd2[kk] * p;
        }
        g_Wd2P[r * 13 + c] = acc;
        if (r == 0) g_bd2P[c] = accb;
    } else {
        // serial teacher-forced control simulation, smem-staged
        __shared__ int sbi[TSTEP * 2];
        __shared__ int sbb[TSTEP];
        __shared__ int slabs[N1];
        __shared__ int s_su[TSTEP], s_sv[TSTEP], s_sb[TSTEP], s_sstate[TSTEP];
        __shared__ unsigned char s_act[TSTEP], s_do[TSTEP];
        __shared__ float s_time[TSTEP];
        __shared__ unsigned long long s_mask[TSTEP];
        __shared__ float s_e[TSTEP * 4];
        __shared__ int s_src[193], s_dst[193];
        if (tid < TSTEP * 2) sbi[tid] = bfsi[tid];
        if (tid < TSTEP) sbb[tid] = bfsb[tid];
        if (tid < N1) slabs[tid] = (tid < NLIG) ? xlab[tid] : 10;
        if (tid < 193) { s_src[tid] = 0; s_dst[tid] = 0; }
        __syncthreads();
        if (tid == 0) {
            const float VALV[11] = {4.f,1.f,3.f,1.f,2.f,1.f,5.f,1.f,6.f,1.f,1000.f};
            const float BV[4] = {1.f,2.f,3.f,1.5f};
            const unsigned long long ALL49 = (1ull << 49) - 1ull;
            float val[N1];
            unsigned long long adj[N1];
            unsigned long long lowm = 0ull, closedm = 0ull;
            int Q[97];
            for (int i = 0; i < N1; i++) {
                val[i] = VALV[slabs[i]];
                adj[i] = 0ull;
                if (val[i] < 1.f) lowm |= (1ull << i);
            }
            int head = 0, tail = 1;
            Q[0] = sbi[0];
            int ne = 0;
            float tf = 0.f;
            s_src[0] = sbi[0];
            s_dst[0] = sbi[1];
            for (int t = 0; t < TSTEP; t++) {
                int v = sbi[t * 2 + 1], b = sbb[t];
                int active = (tail > head) ? 1 : 0;
                s_act[t] = (unsigned char)active;
                s_sv[t] = v; s_sb[t] = b; s_sstate[t] = ne; s_time[t] = tf;
                if (!active) {
                    s_do[t] = 0; s_su[t] = 0; s_mask[t] = 0ull;
                    s_e[t*4] = s_e[t*4+1] = s_e[t*4+2] = s_e[t*4+3] = 0.f;
                    continue;
                }
                int u = Q[head];
                s_su[t] = u;
                bool ulow = ((lowm >> u) & 1ull) != 0ull;
                unsigned long long base = lowm | closedm | adj[u] | (1ull << u);
                unsigned long long mask = ulow ? ALL49 : base;
                mask &= ~((1ull << v) | (1ull << 48));
                s_mask[t] = mask;
                bool mnouv = ulow || (((base >> v) & 1ull) != 0ull);
                int doe = (v != 48);
                s_do[t] = (unsigned char)doe;
                if (doe) {
                    float mv = fminf(val[u], val[v]);
                    float e0 = 0.f, e1 = 0.f, e2 = 0.f, e3 = 0.f;
                    if (mv <= 2.f) { e2 = NEGC; }
                    if (mv <= 1.f) { e0 = 0.f; e1 = NEGC; e2 = NEGC; e3 = 0.f; }
                    if (mv <= 0.f) { e0 = NEGC; e1 = NEGC; e2 = NEGC; e3 = NEGC; }
                    if (mnouv)     { e0 = NEGC; e1 = NEGC; e2 = NEGC; e3 = NEGC; }
                    if (b == 0) e0 = 0.f; else if (b == 1) e1 = 0.f;
                    else if (b == 2) e2 = 0.f; else e3 = 0.f;
                    s_e[t*4] = e0; s_e[t*4+1] = e1; s_e[t*4+2] = e2; s_e[t*4+3] = e3;
                    if (tail < 97) Q[tail] = v;
                    tail++;
                    ne++;
                    s_src[2*ne-1] = u; s_dst[2*ne-1] = v;
                    s_src[2*ne]   = v; s_dst[2*ne]   = u;
                    float dec = BV[b];
                    val[u] -= dec;
                    val[v] -= dec;
                    if (val[u] < 1.f) lowm |= (1ull << u); else lowm &= ~(1ull << u);
                    if (val[v] < 1.f) lowm |= (1ull << v); else lowm &= ~(1ull << v);
                    adj[u] |= (1ull << v);
                    adj[v] |= (1ull << u);
                    tf += 1.f;
                } else {
                    closedm |= (1ull << u);
                    head++;
                    s_e[t*4] = s_e[t*4+1] = s_e[t*4+2] = s_e[t*4+3] = 0.f;
                }
            }
            g_nedges = ne;
        }
        __syncthreads();
        if (tid < TSTEP) {
            g_su[tid] = s_su[tid]; g_sv[tid] = s_sv[tid];
            g_sb[tid] = s_sb[tid]; g_sstate[tid] = s_sstate[tid];
            g_sact[tid] = s_act[tid]; g_sdo[tid] = s_do[tid];
            g_stime[tid] = s_time[tid]; g_smask[tid] = s_mask[tid];
        }
        if (tid < TSTEP * 2) {
            g_se[tid] = s_e[tid];
            g_se[tid + TSTEP * 2] = s_e[tid + TSTEP * 2];
        }
        if (tid < 193) { g_dsrc[tid] = s_src[tid]; g_ddst[tid] = s_dst[tid]; }
    }
}

// ---------------- per-state inner GCN, projected to 13 dims ----------------
#define SMEM_STATES_FLOATS (N1*DD + 637 + 637 + 192 + N1 + N1 + 192 + 192 + N1)
#define SMEM_STATES_BYTES  (SMEM_STATES_FLOATS * 4)

__global__ void k_states(const float* __restrict__ Wd1, const float* __restrict__ bd1) {
    extern __shared__ float sm[];
    float* sh    = sm;                    // 49*256
    float* sg    = sh + N1 * DD;          // 637
    float* sz    = sg + 637;              // 637
    float* wE    = sz + 637;              // 192
    float* sdinv = wE + 192;              // 49
    int* slab = (int*)(sdinv + N1);       // 49
    int* ses  = slab + N1;                // 192
    int* sed  = ses + 192;                // 192
    int* sdeg = sed + 192;                // 49
    int k = blockIdx.x;
    int K = g_nedges;
    if (k > K) return;
    int tid = threadIdx.x;
    int off = (k == 0) ? 0 : 1;
    int cnt = (k == 0) ? 1 : 2 * k;
    if (tid < N1) { slab[tid] = g_lab49[tid]; sdeg[tid] = 0; }
    if (tid < cnt) { ses[tid] = g_dsrc[off + tid]; sed[tid] = g_ddst[off + tid]; }
    __syncthreads();
    if (tid < cnt) atomicAdd(&sdeg[sed[tid]], 1);
    __syncthreads();
    if (tid < N1) sdinv[tid] = rsqrtf((float)(sdeg[tid] + 1));
    __syncthreads();
    if (tid < cnt) wE[tid] = sdinv[ses[tid]] * sdinv[sed[tid]];
    __syncthreads();
    // layer 1 : h = relu(bd1 + self + scatter(Wd1[lab[src]] * norm))
    // column d owned exclusively by thread d
    {
        int d = tid;
        float bd = bd1[d];
        for (int i = 0; i < N1; i++)
            sh[i * DD + d] = bd + Wd1[slab[i] * DD + d] * sdinv[i] * sdinv[i];
        for (int e = 0; e < cnt; e++)
            atomicAdd(&sh[sed[e] * DD + d], Wd1[slab[ses[e]] * DD + d] * wE[e]);
        __syncthreads();
        for (int i = 0; i < N1; i++)
            sh[i * DD + d] = fmaxf(sh[i * DD + d], 0.f);
    }
    __syncthreads();
    // layer 2 projected: sg[i,c] = h[i] @ Wd2P[:,c]
    {
        int w = tid >> 5, lane = tid & 31;
        for (int t = w; t < 637; t += 8) {
            int i = t / 13, c = t - i * 13;
            float p = 0.f;
            for (int d = lane; d < DD; d += 32)
                p += sh[i * DD + d] * g_Wd2P[d * 13 + c];
            for (int o = 16; o; o >>= 1) p += __shfl_xor_sync(0xffffffffu, p, o);
            if (lane == 0) sg[t] = p;
        }
    }
    __syncthreads();
    // self term + bias for ALL 637 entries (BUGFIX: was `if (tid < 637)` with
    // blockDim 256, leaving nodes >= 20 without the self/bias term)
    for (int idx = tid; idx < 637; idx += 256) {
        int i = idx / 13, c = idx - i * 13;
        sz[idx] = g_bd2P[c] + sg[idx] * sdinv[i] * sdinv[i];
    }
    __syncthreads();
    // edge scatter of projections, parallel over (e, c) with smem atomics
    for (int idx = tid; idx < cnt * 13; idx += 256) {
        int e = idx / 13, c = idx - e * 13;
        atomicAdd(&sz[sed[e] * 13 + c], sg[ses[e] * 13 + c] * wE[e]);
    }
    __syncthreads();
    // store ALL 637 (BUGFIX: same guard issue)
    for (int idx = tid; idx < 637; idx += 256)
        g_zP[k * N1 * 13 + idx] = sz[idx];
    if (tid < 13) {
        float s = 0.f;
        for (int i = 0; i < N1; i++) s += sz[i * 13 + tid];
        g_mzP[k * 13 + tid] = s * (1.f / 49.f);
    }
}

// ---------------- final assembly of logp ----------------
__global__ void k_assemble(const float* __restrict__ Wh, float* __restrict__ out) {
    __shared__ float wsum[8];
    int tid = threadIdx.x, w = tid >> 5, lane = tid & 31;
    float acc = 0.f;
    for (int t = w; t < TSTEP; t += 8) {
        if (!g_sact[t]) continue;
        int st = g_sstate[t], v = g_sv[t], u = g_su[t], b = g_sb[t];
        unsigned long long mask = g_smask[t];
        const float* zPs = g_zP + st * N1 * 13;
        // glog softmax over 49 of zP[:,0] + labg + m
        int i0 = lane, i1 = lane + 32;
        float s0 = zPs[i0 * 13] + g_labg[i0] + (((mask >> i0) & 1ull) ? NEGC : 0.f);
        float s1 = (i1 < N1)
                 ? (zPs[i1 * 13] + g_labg[i1] + (((mask >> i1) & 1ull) ? NEGC : 0.f))
                 : -3.0e38f;
        float mx = fmaxf(s0, s1);
        for (int o = 16; o; o >>= 1) mx = fmaxf(mx, __shfl_xor_sync(0xffffffffu, mx, o));
        float se = expf(s0 - mx) + ((i1 < N1) ? expf(s1 - mx) : 0.f);
        for (int o = 16; o; o >>= 1) se += __shfl_xor_sync(0xffffffffu, se, o);
        float sgv = zPs[v * 13] + g_labg[v];     // m[v] == 0 always
        acc += sgv - (mx + logf(se));
        if (g_sdo[t]) {
            int j = lane & 3;
            int lu = g_lab49[u], lv = g_lab49[v];
            float h = g_stime[t] * Wh[j] + g_Apok[j]
                    + zPs[u * 13 + 1 + j] + Wh[(513 + lu) * 4 + j]
                    + zPs[v * 13 + 5 + j] + Wh[(780 + lv) * 4 + j]
                    + g_mzP[st * 13 + 9 + j] + g_CONST[j] + g_se[t * 4 + j];
            float m4 = h;
            m4 = fmaxf(m4, __shfl_xor_sync(0xffffffffu, m4, 1, 4));
            m4 = fmaxf(m4, __shfl_xor_sync(0xffffffffu, m4, 2, 4));
            float s4 = expf(h - m4);
            s4 += __shfl_xor_sync(0xffffffffu, s4, 1, 4);
            s4 += __shfl_xor_sync(0xffffffffu, s4, 2, 4);
            float hb = __shfl_sync(0xffffffffu, h, b, 4);
            acc += hb - (m4 + logf(s4));
        }
    }
    if (lane == 0) wsum[w] = acc;
    __syncthreads();
    if (tid == 0) {
        float s = 0.f;
        for (int i = 0; i < 8; i++) s += wsum[i];
        out[0] = s;
    }
}

// ---------------- launcher ----------------
extern "C" void kernel_launch(void* const* d_in, const int* in_sizes, int n_in,
                              void* d_out, int out_size) {
    (void)in_sizes; (void)n_in; (void)out_size;
    const float* x_p   = (const float*)d_in[0];
    const int*   src_p = (const int*)d_in[1];
    const int*   dst_p = (const int*)d_in[2];
    const float* x_lg  = (const float*)d_in[3];
    const int*   x_ll  = (const int*)d_in[4];
    const int*   src_l = (const int*)d_in[5];
    const int*   dst_l = (const int*)d_in[6];
    const int*   bfsi  = (const int*)d_in[7];
    const int*   bfsb  = (const int*)d_in[8];
    const float* Wp1 = (const float*)d_in[9];
    const float* bp1 = (const float*)d_in[10];
    const float* Wp2 = (const float*)d_in[11];
    const float* bp2 = (const float*)d_in[12];
    const float* Wl1 = (const float*)d_in[13];
    const float* bl1 = (const float*)d_in[14];
    const float* Wl2 = (const float*)d_in[15];
    const float* bl2 = (const float*)d_in[16];
    const float* Wd1 = (const float*)d_in[17];
    const float* bd1 = (const float*)d_in[18];
    const float* Wd2 = (const float*)d_in[19];
    const float* bd2 = (const float*)d_in[20];
    // d_in[21] = Wf, d_in[22] = bf : dead code (logp reset by carry0)
    const float* Wg  = (const float*)d_in[23];
    // d_in[24] = bg : cancels under softmax shift-invariance
    const float* Wh  = (const float*)d_in[25];
    const float* bh  = (const float*)d_in[26];
    float* out = (float*)d_out;

    cudaFuncSetAttribute(k_states, cudaFuncAttributeMaxDynamicSharedMemorySize,
                         SMEM_STATES_BYTES);

    k_zero<<<(NPN + 255) / 256, 256>>>();
    k_deg<<<(EPE + 255) / 256, 256>>>(dst_p);
    k_dinv<<<(NPN + 255) / 256, 256>>>(x_p);
    k_edge<<<(EPE + 255) / 256, 256>>>(x_p, src_p, dst_p);
    k_hred<<<(NPN + 127) / 128, 256>>>(Wp1, bp1);
    k_small<<<16, 256>>>(Wp2, bp2, Wh, x_lg, x_ll, src_l, dst_l,
                         Wl1, bl1, Wl2, bl2, Wg, bh, Wd2, bd2, bfsi, bfsb);
    k_states<<<97, 256, SMEM_STATES_BYTES>>>(Wd1, bd1);
    k_assemble<<<1, 256>>>(Wh, out);
}

// round 12
// speedup vs baseline: 1.6407x; 1.2755x over previous
#include <cuda_runtime.h>
#include <cuda_bf16.h>
#include <math.h>

#define NPN   30000
#define EPE   480000
#define NLIG  48
#define ELIG  144
#define TSTEP 96
#define N1    49
#define DD    256
#define NEGC  (-1.0e9f)

// ---------------- device scratch (static; no allocations) ----------------
__device__ int   g_deg[NPN];
__device__ float g_dinv[NPN];
__device__ __align__(16) float g_y[NPN * 16];    // padded to 16 floats/row
__device__ __align__(16) float g_x16[NPN * 16];  // raw x, padded for LDG.128
__device__ float g_c[NPN];
__device__ float g_t[DD];
__device__ float g_Apok[4];
__device__ float g_CONST[4];     // H_t lab part + H_init + bh
__device__ float g_labg[N1];     // Wg[780 + lab_i]
__device__ int   g_lab49[N1];
__device__ float g_Wd2P[DD * 13];
__device__ float g_bd2P[13];
// sim outputs
__device__ int   g_nedges;
__device__ int   g_dsrc[193], g_ddst[193];
__device__ int   g_su[TSTEP], g_sv[TSTEP], g_sb[TSTEP], g_sstate[TSTEP];
__device__ unsigned char g_sact[TSTEP], g_sdo[TSTEP];
__device__ float g_stime[TSTEP];
__device__ unsigned long long g_smask[TSTEP];
__device__ float g_se[TSTEP * 4];
// per-state projected GCN outputs
__device__ float g_zP[97 * N1 * 13];
__device__ float g_mzP[97 * 13];

__device__ __forceinline__ void red_add_v4(float* p, float a, float b, float c, float d) {
    asm volatile("red.global.add.v4.f32 [%0], {%1, %2, %3, %4};"
                 :: "l"(p), "f"(a), "f"(b), "f"(c), "f"(d) : "memory");
}

// ---------------- pocket GCN (mean only) ----------------
__global__ void k_zero() {
    int i = blockIdx.x * blockDim.x + threadIdx.x;
    if (i < NPN) g_deg[i] = 0;
    if (i < DD) g_t[i] = 0.f;
}

__global__ void k_deg(const int* __restrict__ dst) {
    int e = blockIdx.x * blockDim.x + threadIdx.x;
    if (e < EPE) atomicAdd(&g_deg[dst[e]], 1);
}

__global__ void k_dinv(const float* __restrict__ xp) {
    int i = blockIdx.x * blockDim.x + threadIdx.x;
    if (i >= NPN) return;
    float di = rsqrtf((float)(g_deg[i] + 1));
    g_dinv[i] = di;
    float w = di * di;
    g_c[i] = w;                       // self-loop contribution to c_s
    const float* xr = xp + i * 15;
    float x[16];
#pragma unroll
    for (int k = 0; k < 15; k++) x[k] = xr[k];
    x[15] = 0.f;
    float4* xw = (float4*)(g_x16 + i * 16);
    float4* yr = (float4*)(g_y + i * 16);
#pragma unroll
    for (int q = 0; q < 4; q++) {
        float4 xv = make_float4(x[q*4], x[q*4+1], x[q*4+2], x[q*4+3]);
        xw[q] = xv;
        yr[q] = make_float4(xv.x * w, xv.y * w, xv.z * w, xv.w * w);
    }
}

// 4x LDG.128 gather + 4x RED.v4 scatter per edge (issue-floor optimized)
__global__ void k_edge(const int* __restrict__ src, const int* __restrict__ dst) {
    int e = blockIdx.x * blockDim.x + threadIdx.x;
    if (e >= EPE) return;
    int s = src[e], d = dst[e];
    float nm = g_dinv[s] * g_dinv[d];
    const float4* xs = (const float4*)(g_x16 + s * 16);
    float4 a = xs[0], b = xs[1], c = xs[2], q = xs[3];
    float* yd = g_y + d * 16;
    red_add_v4(yd +  0, a.x * nm, a.y * nm, a.z * nm, a.w * nm);
    red_add_v4(yd +  4, b.x * nm, b.y * nm, b.z * nm, b.w * nm);
    red_add_v4(yd +  8, c.x * nm, c.y * nm, c.z * nm, c.w * nm);
    red_add_v4(yd + 12, q.x * nm, q.y * nm, q.z * nm, q.w * nm);  // q.w = 0
    atomicAdd(&g_c[s], nm);
}

// t[d] = sum_s c_s * relu(y[s]@Wp1[:,d] + bp1[d])
__global__ void k_hred(const float* __restrict__ Wp1, const float* __restrict__ bp1) {
    __shared__ float4 sy4[128 * 4];
    __shared__ float sc[128];
    int n0 = blockIdx.x * 128;
    int nn = min(128, NPN - n0);
    int tid = threadIdx.x;
    float wc[15];
#pragma unroll
    for (int k = 0; k < 15; k++) wc[k] = Wp1[k * DD + tid];
    float b = bp1[tid];
    for (int idx = tid; idx < nn * 4; idx += 256)
        sy4[idx] = ((const float4*)g_y)[n0 * 4 + idx];
    if (tid < nn) sc[tid] = g_c[n0 + tid];
    __syncthreads();
    const float* sy = (const float*)sy4;
    float acc = 0.f;
    for (int j = 0; j < nn; j++) {
        float v = b;
#pragma unroll
        for (int k = 0; k < 15; k++) v += sy[j * 16 + k] * wc[k];
        acc += sc[j] * fmaxf(v, 0.f);
    }
    atomicAdd(&g_t[tid], acc);
}

// ---------------- fused small kernels: zp / ligand / wd2p / sim ----------------
__global__ void k_small(const float* __restrict__ Wp2, const float* __restrict__ bp2,
                        const float* __restrict__ Wh,
                        const float* __restrict__ xg, const int* __restrict__ xlab,
                        const int* __restrict__ srcl, const int* __restrict__ dstl,
                        const float* __restrict__ Wl1, const float* __restrict__ bl1,
                        const float* __restrict__ Wl2, const float* __restrict__ bl2,
                        const float* __restrict__ Wg, const float* __restrict__ bh,
                        const float* __restrict__ Wd2, const float* __restrict__ bd2,
                        const int* __restrict__ bfsi, const int* __restrict__ bfsb) {
    int blk = blockIdx.x;
    int tid = threadIdx.x;
    if (blk == 0) {
        // z_pocket = bp2 + (1/N) t@Wp2 ; Apok_j = z_pocket . Wh[1:257, j]
        __shared__ float st[DD];
        __shared__ float szp[DD];
        st[tid] = g_t[tid];
        __syncthreads();
        float acc = 0.f;
        for (int k = 0; k < DD; k++) acc += st[k] * Wp2[k * DD + tid];
        szp[tid] = bp2[tid] + acc * (1.f / (float)NPN);
        __syncthreads();
        int w = tid >> 5, lane = tid & 31;
        if (w < 4) {
            float p = 0.f;
            for (int d = lane; d < DD; d += 32) p += szp[d] * Wh[(1 + d) * 4 + w];
            for (int o = 16; o; o >>= 1) p += __shfl_xor_sync(0xffffffffu, p, o);
            if (lane == 0) g_Apok[w] = p;
        }
    } else if (blk == 1) {
        // ligand GCN mean + constants
        __shared__ float xl[NLIG * 15];
        __shared__ float yl[NLIG * 15];
        __shared__ float dinv[NLIG], cl[NLIG], tl[DD], mz[DD];
        __shared__ int deg[NLIG], lab[NLIG];
        for (int i = tid; i < NLIG * 15; i += 256) xl[i] = 0.f;
        if (tid < NLIG) { deg[tid] = 0; lab[tid] = xlab[tid]; }
        __syncthreads();
        if (tid < NLIG) {
            for (int k = 0; k < 4; k++) xl[tid * 15 + k] = xg[tid * 4 + k];
            xl[tid * 15 + 4 + lab[tid]] = 1.f;
        }
        __syncthreads();
        if (tid < ELIG) atomicAdd(&deg[dstl[tid]], 1);
        __syncthreads();
        if (tid < NLIG) {
            float di = rsqrtf((float)(deg[tid] + 1));
            dinv[tid] = di;
            cl[tid] = di * di;
            for (int k = 0; k < 15; k++) yl[tid * 15 + k] = xl[tid * 15 + k] * di * di;
        }
        __syncthreads();
        if (tid < ELIG) {
            int s = srcl[tid], d = dstl[tid];
            float nm = dinv[s] * dinv[d];
            for (int k = 0; k < 15; k++) atomicAdd(&yl[d * 15 + k], xl[s * 15 + k] * nm);
            atomicAdd(&cl[s], nm);
        }
        __syncthreads();
        {
            float acc = 0.f;
            float b = bl1[tid];
            for (int s = 0; s < NLIG; s++) {
                float v = b;
#pragma unroll
                for (int k = 0; k < 15; k++) v += yl[s * 15 + k] * Wl1[k * DD + tid];
                acc += cl[s] * fmaxf(v, 0.f);
            }
            tl[tid] = acc;
        }
        __syncthreads();
        {
            float acc = 0.f;
            for (int k = 0; k < DD; k++) acc += tl[k] * Wl2[k * DD + tid];
            mz[tid] = bl2[tid] + acc * (1.f / 48.f);
        }
        __syncthreads();
        if (tid < N1) {
            int l = (tid < NLIG) ? lab[tid] : 10;
            g_lab49[tid] = l;
            g_labg[tid] = Wg[780 + l];
        }
        int w = tid >> 5, lane = tid & 31;
        if (w < 4) {
            int j = w;
            float p = 0.f;
            for (int d = lane; d < DD; d += 32) p += mz[d] * Wh[(1058 + d) * 4 + j];
            for (int n = lane; n < N1; n += 32) {
                int l = (n < NLIG) ? lab[n] : 10;
                p += (1.f / 49.f) * Wh[(1047 + l) * 4 + j];
            }
            for (int n = lane; n < NLIG; n += 32)
                p += (1.f / 48.f) * Wh[(1314 + lab[n]) * 4 + j];
            for (int o = 16; o; o >>= 1) p += __shfl_xor_sync(0xffffffffu, p, o);
            if (lane == 0) g_CONST[j] = p + bh[j];
        }
    } else if (blk < 15) {
        // Wd2 @ P column c = blk-2
        int c = blk - 2;
        int r = tid;
        float acc = 0.f, accb = 0.f;
        for (int kk = 0; kk < DD; kk++) {
            float p;
            if (c == 0)       p = Wg[524 + kk];
            else if (c < 5)   p = Wh[(257 + kk) * 4 + (c - 1)];
            else if (c < 9)   p = Wh[(524 + kk) * 4 + (c - 5)];
            else              p = Wh[(791 + kk) * 4 + (c - 9)];
            acc += Wd2[r * DD + kk] * p;
            if (r == 0) accb += bd2[kk] * p;
        }
        g_Wd2P[r * 13 + c] = acc;
        if (r == 0) g_bd2P[c] = accb;
    } else {
        // serial teacher-forced control simulation, smem-staged
        __shared__ int sbi[TSTEP * 2];
        __shared__ int sbb[TSTEP];
        __shared__ int slabs[N1];
        __shared__ int s_su[TSTEP], s_sv[TSTEP], s_sb[TSTEP], s_sstate[TSTEP];
        __shared__ unsigned char s_act[TSTEP], s_do[TSTEP];
        __shared__ float s_time[TSTEP];
        __shared__ unsigned long long s_mask[TSTEP];
        __shared__ float s_e[TSTEP * 4];
        __shared__ int s_src[193], s_dst[193];
        if (tid < TSTEP * 2) sbi[tid] = bfsi[tid];
        if (tid < TSTEP) sbb[tid] = bfsb[tid];
        if (tid < N1) slabs[tid] = (tid < NLIG) ? xlab[tid] : 10;
        if (tid < 193) { s_src[tid] = 0; s_dst[tid] = 0; }
        __syncthreads();
        if (tid == 0) {
            const float VALV[11] = {4.f,1.f,3.f,1.f,2.f,1.f,5.f,1.f,6.f,1.f,1000.f};
            const float BV[4] = {1.f,2.f,3.f,1.5f};
            const unsigned long long ALL49 = (1ull << 49) - 1ull;
            float val[N1];
            unsigned long long adj[N1];
            unsigned long long lowm = 0ull, closedm = 0ull;
            int Q[97];
            for (int i = 0; i < N1; i++) {
                val[i] = VALV[slabs[i]];
                adj[i] = 0ull;
                if (val[i] < 1.f) lowm |= (1ull << i);
            }
            int head = 0, tail = 1;
            Q[0] = sbi[0];
            int ne = 0;
            float tf = 0.f;
            s_src[0] = sbi[0];
            s_dst[0] = sbi[1];
            for (int t = 0; t < TSTEP; t++) {
                int v = sbi[t * 2 + 1], b = sbb[t];
                int active = (tail > head) ? 1 : 0;
                s_act[t] = (unsigned char)active;
                s_sv[t] = v; s_sb[t] = b; s_sstate[t] = ne; s_time[t] = tf;
                if (!active) {
                    s_do[t] = 0; s_su[t] = 0; s_mask[t] = 0ull;
                    s_e[t*4] = s_e[t*4+1] = s_e[t*4+2] = s_e[t*4+3] = 0.f;
                    continue;
                }
                int u = Q[head];
                s_su[t] = u;
                bool ulow = ((lowm >> u) & 1ull) != 0ull;
                unsigned long long base = lowm | closedm | adj[u] | (1ull << u);
                unsigned long long mask = ulow ? ALL49 : base;
                mask &= ~((1ull << v) | (1ull << 48));
                s_mask[t] = mask;
                bool mnouv = ulow || (((base >> v) & 1ull) != 0ull);
                int doe = (v != 48);
                s_do[t] = (unsigned char)doe;
                if (doe) {
                    float mv = fminf(val[u], val[v]);
                    float e0 = 0.f, e1 = 0.f, e2 = 0.f, e3 = 0.f;
                    if (mv <= 2.f) { e2 = NEGC; }
                    if (mv <= 1.f) { e0 = 0.f; e1 = NEGC; e2 = NEGC; e3 = 0.f; }
                    if (mv <= 0.f) { e0 = NEGC; e1 = NEGC; e2 = NEGC; e3 = NEGC; }
                    if (mnouv)     { e0 = NEGC; e1 = NEGC; e2 = NEGC; e3 = NEGC; }
                    if (b == 0) e0 = 0.f; else if (b == 1) e1 = 0.f;
                    else if (b == 2) e2 = 0.f; else e3 = 0.f;
                    s_e[t*4] = e0; s_e[t*4+1] = e1; s_e[t*4+2] = e2; s_e[t*4+3] = e3;
                    if (tail < 97) Q[tail] = v;
                    tail++;
                    ne++;
                    s_src[2*ne-1] = u; s_dst[2*ne-1] = v;
                    s_src[2*ne]   = v; s_dst[2*ne]   = u;
                    float dec = BV[b];
                    val[u] -= dec;
                    val[v] -= dec;
                    if (val[u] < 1.f) lowm |= (1ull << u); else lowm &= ~(1ull << u);
                    if (val[v] < 1.f) lowm |= (1ull << v); else lowm &= ~(1ull << v);
                    adj[u] |= (1ull << v);
                    adj[v] |= (1ull << u);
                    tf += 1.f;
                } else {
                    closedm |= (1ull << u);
                    head++;
                    s_e[t*4] = s_e[t*4+1] = s_e[t*4+2] = s_e[t*4+3] = 0.f;
                }
            }
            g_nedges = ne;
        }
        __syncthreads();
        if (tid < TSTEP) {
            g_su[tid] = s_su[tid]; g_sv[tid] = s_sv[tid];
            g_sb[tid] = s_sb[tid]; g_sstate[tid] = s_sstate[tid];
            g_sact[tid] = s_act[tid]; g_sdo[tid] = s_do[tid];
            g_stime[tid] = s_time[tid]; g_smask[tid] = s_mask[tid];
        }
        if (tid < TSTEP * 2) {
            g_se[tid] = s_e[tid];
            g_se[tid + TSTEP * 2] = s_e[tid + TSTEP * 2];
        }
        if (tid < 193) { g_dsrc[tid] = s_src[tid]; g_ddst[tid] = s_dst[tid]; }
    }
}

// ---------------- per-state inner GCN, projected to 13 dims ----------------
#define SMEM_STATES_FLOATS (N1*DD + 637 + 637 + 192 + N1 + 11*DD + 13*DD + N1 + 192 + 192 + N1)
#define SMEM_STATES_BYTES  (SMEM_STATES_FLOATS * 4)

__global__ void k_states(const float* __restrict__ Wd1, const float* __restrict__ bd1) {
    extern __shared__ float sm[];
    float* sh    = sm;                    // 49*256
    float* sg    = sh + N1 * DD;          // 637
    float* sz    = sg + 637;              // 637
    float* wE    = sz + 637;              // 192
    float* sdinv = wE + 192;              // 49
    float* sWd1  = sdinv + N1;            // 11*256
    float* sW2   = sWd1 + 11 * DD;        // 13*256 (layout: d*13+c)
    int* slab = (int*)(sW2 + 13 * DD);    // 49
    int* ses  = slab + N1;                // 192
    int* sed  = ses + 192;                // 192
    int* sdeg = sed + 192;                // 49
    int k = blockIdx.x;
    int K = g_nedges;
    if (k > K) return;
    int tid = threadIdx.x;
    int off = (k == 0) ? 0 : 1;
    int cnt = (k == 0) ? 1 : 2 * k;
    if (tid < N1) { slab[tid] = g_lab49[tid]; sdeg[tid] = 0; }
    if (tid < cnt) { ses[tid] = g_dsrc[off + tid]; sed[tid] = g_ddst[off + tid]; }
    for (int i = tid; i < 11 * DD; i += 256) sWd1[i] = Wd1[i];
    for (int i = tid; i < 13 * DD; i += 256) sW2[i] = g_Wd2P[i];
    __syncthreads();
    if (tid < cnt) atomicAdd(&sdeg[sed[tid]], 1);
    __syncthreads();
    if (tid < N1) sdinv[tid] = rsqrtf((float)(sdeg[tid] + 1));
    __syncthreads();
    if (tid < cnt) wE[tid] = sdinv[ses[tid]] * sdinv[sed[tid]];
    __syncthreads();
    // layer 1 : h = relu(bd1 + self + scatter(Wd1[lab[src]] * norm))
    // column d owned exclusively by thread d
    {
        int d = tid;
        float bd = bd1[d];
        for (int i = 0; i < N1; i++)
            sh[i * DD + d] = bd + sWd1[slab[i] * DD + d] * sdinv[i] * sdinv[i];
        for (int e = 0; e < cnt; e++)
            atomicAdd(&sh[sed[e] * DD + d], sWd1[slab[ses[e]] * DD + d] * wE[e]);
        __syncthreads();
        for (int i = 0; i < N1; i++)
            sh[i * DD + d] = fmaxf(sh[i * DD + d], 0.f);
    }
    __syncthreads();
    // layer 2 projected: sg[i,c] = h[i] @ Wd2P[:,c]  (serial dot, no shuffles)
    for (int idx = tid; idx < 637; idx += 256) {
        int i = idx / 13, c = idx - i * 13;
        const float* hrow = sh + i * DD;
        float acc = 0.f;
#pragma unroll 4
        for (int d = 0; d < DD; d++)
            acc += hrow[d] * sW2[d * 13 + c];
        sg[idx] = acc;
    }
    __syncthreads();
    // self term + bias for ALL 637 entries
    for (int idx = tid; idx < 637; idx += 256) {
        int i = idx / 13, c = idx - i * 13;
        sz[idx] = g_bd2P[c] + sg[idx] * sdinv[i] * sdinv[i];
    }
    __syncthreads();
    // edge scatter of projections, parallel over (e, c) with smem atomics
    for (int idx = tid; idx < cnt * 13; idx += 256) {
        int e = idx / 13, c = idx - e * 13;
        atomicAdd(&sz[sed[e] * 13 + c], sg[ses[e] * 13 + c] * wE[e]);
    }
    __syncthreads();
    for (int idx = tid; idx < 637; idx += 256)
        g_zP[k * N1 * 13 + idx] = sz[idx];
    if (tid < 13) {
        float s = 0.f;
        for (int i = 0; i < N1; i++) s += sz[i * 13 + tid];
        g_mzP[k * 13 + tid] = s * (1.f / 49.f);
    }
}

// ---------------- final assembly of logp ----------------
__global__ void k_assemble(const float* __restrict__ Wh, float* __restrict__ out) {
    __shared__ float wsum[8];
    int tid = threadIdx.x, w = tid >> 5, lane = tid & 31;
    float acc = 0.f;
    for (int t = w; t < TSTEP; t += 8) {
        if (!g_sact[t]) continue;
        int st = g_sstate[t], v = g_sv[t], u = g_su[t], b = g_sb[t];
        unsigned long long mask = g_smask[t];
        const float* zPs = g_zP + st * N1 * 13;
        // glog softmax over 49 of zP[:,0] + labg + m
        int i0 = lane, i1 = lane + 32;
        float s0 = zPs[i0 * 13] + g_labg[i0] + (((mask >> i0) & 1ull) ? NEGC : 0.f);
        float s1 = (i1 < N1)
                 ? (zPs[i1 * 13] + g_labg[i1] + (((mask >> i1) & 1ull) ? NEGC : 0.f))
                 : -3.0e38f;
        float mx = fmaxf(s0, s1);
        for (int o = 16; o; o >>= 1) mx = fmaxf(mx, __shfl_xor_sync(0xffffffffu, mx, o));
        float se = expf(s0 - mx) + ((i1 < N1) ? expf(s1 - mx) : 0.f);
        for (int o = 16; o; o >>= 1) se += __shfl_xor_sync(0xffffffffu, se, o);
        float sgv = zPs[v * 13] + g_labg[v];     // m[v] == 0 always
        acc += sgv - (mx + logf(se));
        if (g_sdo[t]) {
            int j = lane & 3;
            int lu = g_lab49[u], lv = g_lab49[v];
            float h = g_stime[t] * Wh[j] + g_Apok[j]
                    + zPs[u * 13 + 1 + j] + Wh[(513 + lu) * 4 + j]
                    + zPs[v * 13 + 5 + j] + Wh[(780 + lv) * 4 + j]
                    + g_mzP[st * 13 + 9 + j] + g_CONST[j] + g_se[t * 4 + j];
            float m4 = h;
            m4 = fmaxf(m4, __shfl_xor_sync(0xffffffffu, m4, 1, 4));
            m4 = fmaxf(m4, __shfl_xor_sync(0xffffffffu, m4, 2, 4));
            float s4 = expf(h - m4);
            s4 += __shfl_xor_sync(0xffffffffu, s4, 1, 4);
            s4 += __shfl_xor_sync(0xffffffffu, s4, 2, 4);
            float hb = __shfl_sync(0xffffffffu, h, b, 4);
            acc += hb - (m4 + logf(s4));
        }
    }
    if (lane == 0) wsum[w] = acc;
    __syncthreads();
    if (tid == 0) {
        float s = 0.f;
        for (int i = 0; i < 8; i++) s += wsum[i];
        out[0] = s;
    }
}

// ---------------- launcher ----------------
extern "C" void kernel_launch(void* const* d_in, const int* in_sizes, int n_in,
                              void* d_out, int out_size) {
    (void)in_sizes; (void)n_in; (void)out_size;
    const float* x_p   = (const float*)d_in[0];
    const int*   src_p = (const int*)d_in[1];
    const int*   dst_p = (const int*)d_in[2];
    const float* x_lg  = (const float*)d_in[3];
    const int*   x_ll  = (const int*)d_in[4];
    const int*   src_l = (const int*)d_in[5];
    const int*   dst_l = (const int*)d_in[6];
    const int*   bfsi  = (const int*)d_in[7];
    const int*   bfsb  = (const int*)d_in[8];
    const float* Wp1 = (const float*)d_in[9];
    const float* bp1 = (const float*)d_in[10];
    const float* Wp2 = (const float*)d_in[11];
    const float* bp2 = (const float*)d_in[12];
    const float* Wl1 = (const float*)d_in[13];
    const float* bl1 = (const float*)d_in[14];
    const float* Wl2 = (const float*)d_in[15];
    const float* bl2 = (const float*)d_in[16];
    const float* Wd1 = (const float*)d_in[17];
    const float* bd1 = (const float*)d_in[18];
    const float* Wd2 = (const float*)d_in[19];
    const float* bd2 = (const float*)d_in[20];
    // d_in[21] = Wf, d_in[22] = bf : dead code (logp reset by carry0)
    const float* Wg  = (const float*)d_in[23];
    // d_in[24] = bg : cancels under softmax shift-invariance
    const float* Wh  = (const float*)d_in[25];
    const float* bh  = (const float*)d_in[26];
    float* out = (float*)d_out;

    cudaFuncSetAttribute(k_states, cudaFuncAttributeMaxDynamicSharedMemorySize,
                         SMEM_STATES_BYTES);

    k_zero<<<(NPN + 255) / 256, 256>>>();
    k_deg<<<(EPE + 255) / 256, 256>>>(dst_p);
    k_dinv<<<(NPN + 255) / 256, 256>>>(x_p);
    k_edge<<<(EPE + 255) / 256, 256>>>(src_p, dst_p);
    k_hred<<<(NPN + 127) / 128, 256>>>(Wp1, bp1);
    k_small<<<16, 256>>>(Wp2, bp2, Wh, x_lg, x_ll, src_l, dst_l,
                         Wl1, bl1, Wl2, bl2, Wg, bh, Wd2, bd2, bfsi, bfsb);
    k_states<<<97, 256, SMEM_STATES_BYTES>>>(Wd1, bd1);
    k_assemble<<<1, 256>>>(Wh, out);
}

// round 13
// speedup vs baseline: 2.1492x; 1.3099x over previous
#include <cuda_runtime.h>
#include <cuda_bf16.h>
#include <math.h>

#define NPN   30000
#define EPE   480000
#define NLIG  48
#define ELIG  144
#define TSTEP 96
#define N1    49
#define DD    256
#define NEGC  (-1.0e9f)

// ---------------- device scratch (static; no allocations) ----------------
__device__ int   g_deg[NPN];
__device__ float g_dinv[NPN];
__device__ __align__(16) float g_y[NPN * 16];    // padded to 16 floats/row
__device__ __align__(16) float g_x16[NPN * 16];  // raw x, padded for LDG.128
__device__ float g_c[NPN];
__device__ float g_t[DD];
__device__ float g_Apok[4];
__device__ float g_CONST[4];     // H_t lab part + H_init + bh
__device__ float g_labg[N1];     // Wg[780 + lab_i]
__device__ int   g_lab49[N1];
__device__ float g_Wd2P[DD * 13];
__device__ float g_bd2P[13];
// sim outputs
__device__ int   g_nedges;
__device__ int   g_dsrc[193], g_ddst[193];
__device__ int   g_su[TSTEP], g_sv[TSTEP], g_sb[TSTEP], g_sstate[TSTEP];
__device__ unsigned char g_sact[TSTEP], g_sdo[TSTEP];
__device__ float g_stime[TSTEP];
__device__ unsigned long long g_smask[TSTEP];
__device__ float g_se[TSTEP * 4];
// per-state projected GCN outputs
__device__ float g_zP[97 * N1 * 13];
__device__ float g_mzP[97 * 13];

__device__ __forceinline__ void red_add_v4(float* p, float a, float b, float c, float d) {
    asm volatile("red.global.add.v4.f32 [%0], {%1, %2, %3, %4};"
                 :: "l"(p), "f"(a), "f"(b), "f"(c), "f"(d) : "memory");
}

// ---------------- pocket GCN (mean only) ----------------
__global__ void k_zero() {
    int i = blockIdx.x * blockDim.x + threadIdx.x;
    if (i < NPN) g_deg[i] = 0;
    if (i < DD) g_t[i] = 0.f;
}

__global__ void k_deg(const int* __restrict__ dst) {
    int e = blockIdx.x * blockDim.x + threadIdx.x;
    if (e < EPE) atomicAdd(&g_deg[dst[e]], 1);
}

__global__ void k_dinv(const float* __restrict__ xp) {
    int i = blockIdx.x * blockDim.x + threadIdx.x;
    if (i >= NPN) return;
    float di = rsqrtf((float)(g_deg[i] + 1));
    g_dinv[i] = di;
    float w = di * di;
    g_c[i] = w;                       // self-loop contribution to c_s
    const float* xr = xp + i * 15;
    float x[16];
#pragma unroll
    for (int k = 0; k < 15; k++) x[k] = xr[k];
    x[15] = 0.f;
    float4* xw = (float4*)(g_x16 + i * 16);
    float4* yr = (float4*)(g_y + i * 16);
#pragma unroll
    for (int q = 0; q < 4; q++) {
        float4 xv = make_float4(x[q*4], x[q*4+1], x[q*4+2], x[q*4+3]);
        xw[q] = xv;
        yr[q] = make_float4(xv.x * w, xv.y * w, xv.z * w, xv.w * w);
    }
}

// 4x LDG.128 gather + 4x RED.v4 scatter per edge (issue-floor optimized)
__global__ void k_edge(const int* __restrict__ src, const int* __restrict__ dst) {
    int e = blockIdx.x * blockDim.x + threadIdx.x;
    if (e >= EPE) return;
    int s = src[e], d = dst[e];
    float nm = g_dinv[s] * g_dinv[d];
    const float4* xs = (const float4*)(g_x16 + s * 16);
    float4 a = xs[0], b = xs[1], c = xs[2], q = xs[3];
    float* yd = g_y + d * 16;
    red_add_v4(yd +  0, a.x * nm, a.y * nm, a.z * nm, a.w * nm);
    red_add_v4(yd +  4, b.x * nm, b.y * nm, b.z * nm, b.w * nm);
    red_add_v4(yd +  8, c.x * nm, c.y * nm, c.z * nm, c.w * nm);
    red_add_v4(yd + 12, q.x * nm, q.y * nm, q.z * nm, q.w * nm);  // q.w = 0
    atomicAdd(&g_c[s], nm);
}

// t[d] = sum_s c_s * relu(y[s]@Wp1[:,d] + bp1[d])
__global__ void k_hred(const float* __restrict__ Wp1, const float* __restrict__ bp1) {
    __shared__ float4 sy4[128 * 4];
    __shared__ float sc[128];
    int n0 = blockIdx.x * 128;
    int nn = min(128, NPN - n0);
    int tid = threadIdx.x;
    float wc[16];
#pragma unroll
    for (int k = 0; k < 15; k++) wc[k] = Wp1[k * DD + tid];
    wc[15] = 0.f;
    float b = bp1[tid];
    for (int idx = tid; idx < nn * 4; idx += 256)
        sy4[idx] = ((const float4*)g_y)[n0 * 4 + idx];
    if (tid < nn) sc[tid] = g_c[n0 + tid];
    __syncthreads();
    float acc = 0.f;
    for (int j = 0; j < nn; j++) {
        float4 a = sy4[j*4+0], bb = sy4[j*4+1], c = sy4[j*4+2], q = sy4[j*4+3];
        float v = b;
        v += a.x*wc[0] + a.y*wc[1] + a.z*wc[2] + a.w*wc[3];
        v += bb.x*wc[4] + bb.y*wc[5] + bb.z*wc[6] + bb.w*wc[7];
        v += c.x*wc[8] + c.y*wc[9] + c.z*wc[10] + c.w*wc[11];
        v += q.x*wc[12] + q.y*wc[13] + q.z*wc[14];   // q.w is pad (0)
        acc += sc[j] * fmaxf(v, 0.f);
    }
    atomicAdd(&g_t[tid], acc);
}

// z_pocket = bp2 + (1/N) t@Wp2 ; Apok_j = z_pocket . Wh[1:257, j]
__global__ void k_zp(const float* __restrict__ Wp2, const float* __restrict__ bp2,
                     const float* __restrict__ Wh) {
    __shared__ float st[DD];
    __shared__ float szp[DD];
    int tid = threadIdx.x;
    st[tid] = g_t[tid];
    __syncthreads();
    float acc = 0.f;
    for (int k = 0; k < DD; k++) acc += st[k] * Wp2[k * DD + tid];
    szp[tid] = bp2[tid] + acc * (1.f / (float)NPN);
    __syncthreads();
    int w = tid >> 5, lane = tid & 31;
    if (w < 4) {
        float p = 0.f;
        for (int d = lane; d < DD; d += 32) p += szp[d] * Wh[(1 + d) * 4 + w];
        for (int o = 16; o; o >>= 1) p += __shfl_xor_sync(0xffffffffu, p, o);
        if (lane == 0) g_Apok[w] = p;
    }
}

// ---------------- chain B: ligand / wd2p(single block, coalesced) / sim ----------------
__global__ void k_smallB(const float* __restrict__ Wh,
                         const float* __restrict__ xg, const int* __restrict__ xlab,
                         const int* __restrict__ srcl, const int* __restrict__ dstl,
                         const float* __restrict__ Wl1, const float* __restrict__ bl1,
                         const float* __restrict__ Wl2, const float* __restrict__ bl2,
                         const float* __restrict__ Wg, const float* __restrict__ bh,
                         const float* __restrict__ Wd2, const float* __restrict__ bd2,
                         const int* __restrict__ bfsi, const int* __restrict__ bfsb) {
    int blk = blockIdx.x;
    int tid = threadIdx.x;
    if (blk == 0) {
        // ligand GCN mean + constants
        __shared__ float xl[NLIG * 15];
        __shared__ float yl[NLIG * 15];
        __shared__ float dinv[NLIG], cl[NLIG], tl[DD], mz[DD];
        __shared__ int deg[NLIG], lab[NLIG];
        for (int i = tid; i < NLIG * 15; i += 256) xl[i] = 0.f;
        if (tid < NLIG) { deg[tid] = 0; lab[tid] = xlab[tid]; }
        __syncthreads();
        if (tid < NLIG) {
            for (int k = 0; k < 4; k++) xl[tid * 15 + k] = xg[tid * 4 + k];
            xl[tid * 15 + 4 + lab[tid]] = 1.f;
        }
        __syncthreads();
        if (tid < ELIG) atomicAdd(&deg[dstl[tid]], 1);
        __syncthreads();
        if (tid < NLIG) {
            float di = rsqrtf((float)(deg[tid] + 1));
            dinv[tid] = di;
            cl[tid] = di * di;
            for (int k = 0; k < 15; k++) yl[tid * 15 + k] = xl[tid * 15 + k] * di * di;
        }
        __syncthreads();
        if (tid < ELIG) {
            int s = srcl[tid], d = dstl[tid];
            float nm = dinv[s] * dinv[d];
            for (int k = 0; k < 15; k++) atomicAdd(&yl[d * 15 + k], xl[s * 15 + k] * nm);
            atomicAdd(&cl[s], nm);
        }
        __syncthreads();
        {
            float acc = 0.f;
            float b = bl1[tid];
            for (int s = 0; s < NLIG; s++) {
                float v = b;
#pragma unroll
                for (int k = 0; k < 15; k++) v += yl[s * 15 + k] * Wl1[k * DD + tid];
                acc += cl[s] * fmaxf(v, 0.f);
            }
            tl[tid] = acc;
        }
        __syncthreads();
        {
            float acc = 0.f;
            for (int k = 0; k < DD; k++) acc += tl[k] * Wl2[k * DD + tid];
            mz[tid] = bl2[tid] + acc * (1.f / 48.f);
        }
        __syncthreads();
        if (tid < N1) {
            int l = (tid < NLIG) ? lab[tid] : 10;
            g_lab49[tid] = l;
            g_labg[tid] = Wg[780 + l];
        }
        int w = tid >> 5, lane = tid & 31;
        if (w < 4) {
            int j = w;
            float p = 0.f;
            for (int d = lane; d < DD; d += 32) p += mz[d] * Wh[(1058 + d) * 4 + j];
            for (int n = lane; n < N1; n += 32) {
                int l = (n < NLIG) ? lab[n] : 10;
                p += (1.f / 49.f) * Wh[(1047 + l) * 4 + j];
            }
            for (int n = lane; n < NLIG; n += 32)
                p += (1.f / 48.f) * Wh[(1314 + lab[n]) * 4 + j];
            for (int o = 16; o; o >>= 1) p += __shfl_xor_sync(0xffffffffu, p, o);
            if (lane == 0) g_CONST[j] = p + bh[j];
        }
    } else if (blk == 1) {
        // Wd2P = Wd2 @ P, single block, coalesced via smem transpose tiles
        __shared__ float sP[DD * 13];        // P[kk][c]
        __shared__ float tile[16 * 257];     // transposed Wd2 chunk: [j][r]
        for (int idx = tid; idx < DD * 13; idx += 256) {
            int kk = idx / 13, c = idx - kk * 13;
            float p;
            if (c == 0)       p = Wg[524 + kk];
            else if (c < 5)   p = Wh[(257 + kk) * 4 + (c - 1)];
            else if (c < 9)   p = Wh[(524 + kk) * 4 + (c - 5)];
            else              p = Wh[(791 + kk) * 4 + (c - 9)];
            sP[idx] = p;
        }
        __syncthreads();
        float acc[13];
#pragma unroll
        for (int c = 0; c < 13; c++) acc[c] = 0.f;
        for (int kk0 = 0; kk0 < DD; kk0 += 16) {
            // coalesced load of Wd2[:, kk0:kk0+16] -> tile[j][r]
            for (int q = tid; q < 1024; q += 256) {      // 1024 float4 = 4096 floats
                int r = q >> 2, j4 = q & 3;
                float4 v = *(const float4*)(Wd2 + r * DD + kk0 + j4 * 4);
                tile[(j4 * 4 + 0) * 257 + r] = v.x;
                tile[(j4 * 4 + 1) * 257 + r] = v.y;
                tile[(j4 * 4 + 2) * 257 + r] = v.z;
                tile[(j4 * 4 + 3) * 257 + r] = v.w;
            }
            __syncthreads();
#pragma unroll
            for (int j = 0; j < 16; j++) {
                float w = tile[j * 257 + tid];
                const float* p = &sP[(kk0 + j) * 13];
#pragma unroll
                for (int c = 0; c < 13; c++) acc[c] += w * p[c];
            }
            __syncthreads();
        }
#pragma unroll
        for (int c = 0; c < 13; c++) g_Wd2P[tid * 13 + c] = acc[c];
        if (tid < 13) {
            float s = 0.f;
            for (int kk = 0; kk < DD; kk++) s += bd2[kk] * sP[kk * 13 + tid];
            g_bd2P[tid] = s;
        }
    } else {
        // serial teacher-forced control simulation, smem-staged
        __shared__ int sbi[TSTEP * 2];
        __shared__ int sbb[TSTEP];
        __shared__ int slabs[N1];
        __shared__ int s_su[TSTEP], s_sv[TSTEP], s_sb[TSTEP], s_sstate[TSTEP];
        __shared__ unsigned char s_act[TSTEP], s_do[TSTEP];
        __shared__ float s_time[TSTEP];
        __shared__ unsigned long long s_mask[TSTEP];
        __shared__ float s_e[TSTEP * 4];
        __shared__ int s_src[193], s_dst[193];
        if (tid < TSTEP * 2) sbi[tid] = bfsi[tid];
        if (tid < TSTEP) sbb[tid] = bfsb[tid];
        if (tid < N1) slabs[tid] = (tid < NLIG) ? xlab[tid] : 10;
        if (tid < 193) { s_src[tid] = 0; s_dst[tid] = 0; }
        __syncthreads();
        if (tid == 0) {
            const float VALV[11] = {4.f,1.f,3.f,1.f,2.f,1.f,5.f,1.f,6.f,1.f,1000.f};
            const float BV[4] = {1.f,2.f,3.f,1.5f};
            const unsigned long long ALL49 = (1ull << 49) - 1ull;
            float val[N1];
            unsigned long long adj[N1];
            unsigned long long lowm = 0ull, closedm = 0ull;
            int Q[97];
            for (int i = 0; i < N1; i++) {
                val[i] = VALV[slabs[i]];
                adj[i] = 0ull;
                if (val[i] < 1.f) lowm |= (1ull << i);
            }
            int head = 0, tail = 1;
            Q[0] = sbi[0];
            int ne = 0;
            float tf = 0.f;
            s_src[0] = sbi[0];
            s_dst[0] = sbi[1];
            for (int t = 0; t < TSTEP; t++) {
                int v = sbi[t * 2 + 1], b = sbb[t];
                int active = (tail > head) ? 1 : 0;
                s_act[t] = (unsigned char)active;
                s_sv[t] = v; s_sb[t] = b; s_sstate[t] = ne; s_time[t] = tf;
                if (!active) {
                    s_do[t] = 0; s_su[t] = 0; s_mask[t] = 0ull;
                    s_e[t*4] = s_e[t*4+1] = s_e[t*4+2] = s_e[t*4+3] = 0.f;
                    continue;
                }
                int u = Q[head];
                s_su[t] = u;
                bool ulow = ((lowm >> u) & 1ull) != 0ull;
                unsigned long long base = lowm | closedm | adj[u] | (1ull << u);
                unsigned long long mask = ulow ? ALL49 : base;
                mask &= ~((1ull << v) | (1ull << 48));
                s_mask[t] = mask;
                bool mnouv = ulow || (((base >> v) & 1ull) != 0ull);
                int doe = (v != 48);
                s_do[t] = (unsigned char)doe;
                if (doe) {
                    float mv = fminf(val[u], val[v]);
                    float e0 = 0.f, e1 = 0.f, e2 = 0.f, e3 = 0.f;
                    if (mv <= 2.f) { e2 = NEGC; }
                    if (mv <= 1.f) { e0 = 0.f; e1 = NEGC; e2 = NEGC; e3 = 0.f; }
                    if (mv <= 0.f) { e0 = NEGC; e1 = NEGC; e2 = NEGC; e3 = NEGC; }
                    if (mnouv)     { e0 = NEGC; e1 = NEGC; e2 = NEGC; e3 = NEGC; }
                    if (b == 0) e0 = 0.f; else if (b == 1) e1 = 0.f;
                    else if (b == 2) e2 = 0.f; else e3 = 0.f;
                    s_e[t*4] = e0; s_e[t*4+1] = e1; s_e[t*4+2] = e2; s_e[t*4+3] = e3;
                    if (tail < 97) Q[tail] = v;
                    tail++;
                    ne++;
                    s_src[2*ne-1] = u; s_dst[2*ne-1] = v;
                    s_src[2*ne]   = v; s_dst[2*ne]   = u;
                    float dec = BV[b];
                    val[u] -= dec;
                    val[v] -= dec;
                    if (val[u] < 1.f) lowm |= (1ull << u); else lowm &= ~(1ull << u);
                    if (val[v] < 1.f) lowm |= (1ull << v); else lowm &= ~(1ull << v);
                    adj[u] |= (1ull << v);
                    adj[v] |= (1ull << u);
                    tf += 1.f;
                } else {
                    closedm |= (1ull << u);
                    head++;
                    s_e[t*4] = s_e[t*4+1] = s_e[t*4+2] = s_e[t*4+3] = 0.f;
                }
            }
            g_nedges = ne;
        }
        __syncthreads();
        if (tid < TSTEP) {
            g_su[tid] = s_su[tid]; g_sv[tid] = s_sv[tid];
            g_sb[tid] = s_sb[tid]; g_sstate[tid] = s_sstate[tid];
            g_sact[tid] = s_act[tid]; g_sdo[tid] = s_do[tid];
            g_stime[tid] = s_time[tid]; g_smask[tid] = s_mask[tid];
        }
        if (tid < TSTEP * 2) {
            g_se[tid] = s_e[tid];
            g_se[tid + TSTEP * 2] = s_e[tid + TSTEP * 2];
        }
        if (tid < 193) { g_dsrc[tid] = s_src[tid]; g_ddst[tid] = s_dst[tid]; }
    }
}

// ---------------- per-state inner GCN, projected to 13 dims ----------------
#define SMEM_STATES_FLOATS (N1*DD + 637 + 637 + 192 + N1 + 11*DD + 13*DD + N1 + 192 + 192 + N1)
#define SMEM_STATES_BYTES  (SMEM_STATES_FLOATS * 4)

__global__ void k_states(const float* __restrict__ Wd1, const float* __restrict__ bd1) {
    extern __shared__ float sm[];
    float* sh    = sm;                    // 49*256
    float* sg    = sh + N1 * DD;          // 637
    float* sz    = sg + 637;              // 637
    float* wE    = sz + 637;              // 192
    float* sdinv = wE + 192;              // 49
    float* sWd1  = sdinv + N1;            // 11*256
    float* sW2   = sWd1 + 11 * DD;        // 13*256 (layout: d*13+c)
    int* slab = (int*)(sW2 + 13 * DD);    // 49
    int* ses  = slab + N1;                // 192
    int* sed  = ses + 192;                // 192
    int* sdeg = sed + 192;                // 49
    int k = blockIdx.x;
    int K = g_nedges;
    if (k > K) return;
    int tid = threadIdx.x;
    int off = (k == 0) ? 0 : 1;
    int cnt = (k == 0) ? 1 : 2 * k;
    if (tid < N1) { slab[tid] = g_lab49[tid]; sdeg[tid] = 0; }
    if (tid < cnt) { ses[tid] = g_dsrc[off + tid]; sed[tid] = g_ddst[off + tid]; }
    for (int i = tid; i < 11 * DD; i += 256) sWd1[i] = Wd1[i];
    for (int i = tid; i < 13 * DD; i += 256) sW2[i] = g_Wd2P[i];
    __syncthreads();
    if (tid < cnt) atomicAdd(&sdeg[sed[tid]], 1);
    __syncthreads();
    if (tid < N1) sdinv[tid] = rsqrtf((float)(sdeg[tid] + 1));
    __syncthreads();
    if (tid < cnt) wE[tid] = sdinv[ses[tid]] * sdinv[sed[tid]];
    __syncthreads();
    // layer 1 : h = relu(bd1 + self + scatter(Wd1[lab[src]] * norm))
    // column d owned EXCLUSIVELY by thread d -> plain RMW, no atomics needed
    {
        int d = tid;
        float bd = bd1[d];
        for (int i = 0; i < N1; i++)
            sh[i * DD + d] = bd + sWd1[slab[i] * DD + d] * sdinv[i] * sdinv[i];
        for (int e = 0; e < cnt; e++)
            sh[sed[e] * DD + d] += sWd1[slab[ses[e]] * DD + d] * wE[e];
        for (int i = 0; i < N1; i++)
            sh[i * DD + d] = fmaxf(sh[i * DD + d], 0.f);
    }
    __syncthreads();
    // layer 2 projected: sg[i,c] = h[i] @ Wd2P[:,c]  (serial dot, no shuffles)
    for (int idx = tid; idx < 637; idx += 256) {
        int i = idx / 13, c = idx - i * 13;
        const float* hrow = sh + i * DD;
        float acc = 0.f;
#pragma unroll 4
        for (int d = 0; d < DD; d++)
            acc += hrow[d] * sW2[d * 13 + c];
        sg[idx] = acc;
    }
    __syncthreads();
    // self term + bias for ALL 637 entries
    for (int idx = tid; idx < 637; idx += 256) {
        int i = idx / 13, c = idx - i * 13;
        sz[idx] = g_bd2P[c] + sg[idx] * sdinv[i] * sdinv[i];
    }
    __syncthreads();
    // edge scatter of projections, parallel over (e, c) with smem atomics
    for (int idx = tid; idx < cnt * 13; idx += 256) {
        int e = idx / 13, c = idx - e * 13;
        atomicAdd(&sz[sed[e] * 13 + c], sg[ses[e] * 13 + c] * wE[e]);
    }
    __syncthreads();
    for (int idx = tid; idx < 637; idx += 256)
        g_zP[k * N1 * 13 + idx] = sz[idx];
    if (tid < 13) {
        float s = 0.f;
        for (int i = 0; i < N1; i++) s += sz[i * 13 + tid];
        g_mzP[k * 13 + tid] = s * (1.f / 49.f);
    }
}

// ---------------- final assembly of logp ----------------
__global__ void k_assemble(const float* __restrict__ Wh, float* __restrict__ out) {
    __shared__ float wsum[8];
    int tid = threadIdx.x, w = tid >> 5, lane = tid & 31;
    float acc = 0.f;
    for (int t = w; t < TSTEP; t += 8) {
        if (!g_sact[t]) continue;
        int st = g_sstate[t], v = g_sv[t], u = g_su[t], b = g_sb[t];
        unsigned long long mask = g_smask[t];
        const float* zPs = g_zP + st * N1 * 13;
        // glog softmax over 49 of zP[:,0] + labg + m
        int i0 = lane, i1 = lane + 32;
        float s0 = zPs[i0 * 13] + g_labg[i0] + (((mask >> i0) & 1ull) ? NEGC : 0.f);
        float s1 = (i1 < N1)
                 ? (zPs[i1 * 13] + g_labg[i1] + (((mask >> i1) & 1ull) ? NEGC : 0.f))
                 : -3.0e38f;
        float mx = fmaxf(s0, s1);
        for (int o = 16; o; o >>= 1) mx = fmaxf(mx, __shfl_xor_sync(0xffffffffu, mx, o));
        float se = expf(s0 - mx) + ((i1 < N1) ? expf(s1 - mx) : 0.f);
        for (int o = 16; o; o >>= 1) se += __shfl_xor_sync(0xffffffffu, se, o);
        float sgv = zPs[v * 13] + g_labg[v];     // m[v] == 0 always
        acc += sgv - (mx + logf(se));
        if (g_sdo[t]) {
            int j = lane & 3;
            int lu = g_lab49[u], lv = g_lab49[v];
            float h = g_stime[t] * Wh[j] + g_Apok[j]
                    + zPs[u * 13 + 1 + j] + Wh[(513 + lu) * 4 + j]
                    + zPs[v * 13 + 5 + j] + Wh[(780 + lv) * 4 + j]
                    + g_mzP[st * 13 + 9 + j] + g_CONST[j] + g_se[t * 4 + j];
            float m4 = h;
            m4 = fmaxf(m4, __shfl_xor_sync(0xffffffffu, m4, 1, 4));
            m4 = fmaxf(m4, __shfl_xor_sync(0xffffffffu, m4, 2, 4));
            float s4 = expf(h - m4);
            s4 += __shfl_xor_sync(0xffffffffu, s4, 1, 4);
            s4 += __shfl_xor_sync(0xffffffffu, s4, 2, 4);
            float hb = __shfl_sync(0xffffffffu, h, b, 4);
            acc += hb - (m4 + logf(s4));
        }
    }
    if (lane == 0) wsum[w] = acc;
    __syncthreads();
    if (tid == 0) {
        float s = 0.f;
        for (int i = 0; i < 8; i++) s += wsum[i];
        out[0] = s;
    }
}

// ---------------- launcher (fork-join: pocket chain || ligand/sim/states) ----------------
extern "C" void kernel_launch(void* const* d_in, const int* in_sizes, int n_in,
                              void* d_out, int out_size) {
    (void)in_sizes; (void)n_in; (void)out_size;
    const float* x_p   = (const float*)d_in[0];
    const int*   src_p = (const int*)d_in[1];
    const int*   dst_p = (const int*)d_in[2];
    const float* x_lg  = (const float*)d_in[3];
    const int*   x_ll  = (const int*)d_in[4];
    const int*   src_l = (const int*)d_in[5];
    const int*   dst_l = (const int*)d_in[6];
    const int*   bfsi  = (const int*)d_in[7];
    const int*   bfsb  = (const int*)d_in[8];
    const float* Wp1 = (const float*)d_in[9];
    const float* bp1 = (const float*)d_in[10];
    const float* Wp2 = (const float*)d_in[11];
    const float* bp2 = (const float*)d_in[12];
    const float* Wl1 = (const float*)d_in[13];
    const float* bl1 = (const float*)d_in[14];
    const float* Wl2 = (const float*)d_in[15];
    const float* bl2 = (const float*)d_in[16];
    const float* Wd1 = (const float*)d_in[17];
    const float* bd1 = (const float*)d_in[18];
    const float* Wd2 = (const float*)d_in[19];
    const float* bd2 = (const float*)d_in[20];
    // d_in[21] = Wf, d_in[22] = bf : dead code (logp reset by carry0)
    const float* Wg  = (const float*)d_in[23];
    // d_in[24] = bg : cancels under softmax shift-invariance
    const float* Wh  = (const float*)d_in[25];
    const float* bh  = (const float*)d_in[26];
    float* out = (float*)d_out;

    cudaFuncSetAttribute(k_states, cudaFuncAttributeMaxDynamicSharedMemorySize,
                         SMEM_STATES_BYTES);

    cudaStream_t sB;
    cudaEvent_t eFork, eJoin;
    cudaStreamCreateWithFlags(&sB, cudaStreamNonBlocking);
    cudaEventCreateWithFlags(&eFork, cudaEventDisableTiming);
    cudaEventCreateWithFlags(&eJoin, cudaEventDisableTiming);

    cudaEventRecord(eFork, 0);
    cudaStreamWaitEvent(sB, eFork, 0);

    // chain B (independent of pocket): ligand/wd2p/sim -> per-state GCN
    k_smallB<<<3, 256, 0, sB>>>(Wh, x_lg, x_ll, src_l, dst_l,
                                Wl1, bl1, Wl2, bl2, Wg, bh, Wd2, bd2, bfsi, bfsb);
    k_states<<<97, 256, SMEM_STATES_BYTES, sB>>>(Wd1, bd1);
    cudaEventRecord(eJoin, sB);

    // chain A (pocket GCN mean)
    k_zero<<<(NPN + 255) / 256, 256>>>();
    k_deg<<<(EPE + 255) / 256, 256>>>(dst_p);
    k_dinv<<<(NPN + 255) / 256, 256>>>(x_p);
    k_edge<<<(EPE + 255) / 256, 256>>>(src_p, dst_p);
    k_hred<<<(NPN + 127) / 128, 256>>>(Wp1, bp1);
    k_zp<<<1, 256>>>(Wp2, bp2, Wh);

    // join and assemble
    cudaStreamWaitEvent(0, eJoin, 0);
    k_assemble<<<1, 256>>>(Wh, out);
}

// round 14
// speedup vs baseline: 2.1517x; 1.0012x over previous
#include <cuda_runtime.h>
#include <cuda_bf16.h>
#include <math.h>

#define NPN   30000
#define EPE   480000
#define NLIG  48
#define ELIG  144
#define TSTEP 96
#define N1    49
#define DD    256
#define NEGC  (-1.0e9f)

// ---------------- device scratch (static; no allocations) ----------------
__device__ int   g_deg[NPN];
__device__ float g_dinv[NPN];
__device__ __align__(16) float g_y[NPN * 16];    // padded to 16 floats/row
__device__ __align__(16) float g_x16[NPN * 16];  // raw x, padded for LDG.128
__device__ float g_c[NPN];
__device__ float g_t[DD];
__device__ unsigned int g_ctr;
__device__ float g_Apok[4];
__device__ float g_CONST[4];     // H_t lab part + H_init + bh
__device__ float g_labg[N1];     // Wg[780 + lab_i]
__device__ int   g_lab49[N1];
__device__ float g_Wd2P[DD * 13];
__device__ float g_bd2P[13];
// sim outputs
__device__ int   g_nedges;
__device__ int   g_dsrc[193], g_ddst[193];
__device__ int   g_su[TSTEP], g_sv[TSTEP], g_sb[TSTEP], g_sstate[TSTEP];
__device__ unsigned char g_sact[TSTEP], g_sdo[TSTEP];
__device__ float g_stime[TSTEP];
__device__ unsigned long long g_smask[TSTEP];
__device__ float g_se[TSTEP * 4];
// per-state projected GCN outputs
__device__ float g_zP[97 * N1 * 13];
__device__ float g_mzP[97 * 13];

__device__ __forceinline__ void red_add_v4(float* p, float a, float b, float c, float d) {
    asm volatile("red.global.add.v4.f32 [%0], {%1, %2, %3, %4};"
                 :: "l"(p), "f"(a), "f"(b), "f"(c), "f"(d) : "memory");
}

// ---------------- pocket GCN (mean only) ----------------
__global__ void k_deg(const int* __restrict__ dst) {
    int e = blockIdx.x * blockDim.x + threadIdx.x;
    if (e < EPE) atomicAdd(&g_deg[dst[e]], 1);
}

__global__ void k_dinv(const float* __restrict__ xp) {
    int i = blockIdx.x * blockDim.x + threadIdx.x;
    if (i >= NPN) return;
    float di = rsqrtf((float)(g_deg[i] + 1));
    g_deg[i] = 0;                     // self-clean for next graph replay
    g_dinv[i] = di;
    float w = di * di;
    g_c[i] = w;                       // self-loop contribution to c_s
    const float* xr = xp + i * 15;
    float x[16];
#pragma unroll
    for (int k = 0; k < 15; k++) x[k] = xr[k];
    x[15] = 0.f;
    float4* xw = (float4*)(g_x16 + i * 16);
    float4* yr = (float4*)(g_y + i * 16);
#pragma unroll
    for (int q = 0; q < 4; q++) {
        float4 xv = make_float4(x[q*4], x[q*4+1], x[q*4+2], x[q*4+3]);
        xw[q] = xv;
        yr[q] = make_float4(xv.x * w, xv.y * w, xv.z * w, xv.w * w);
    }
}

// 4x LDG.128 gather + 4x RED.v4 scatter per edge (issue-floor optimized)
__global__ void k_edge(const int* __restrict__ src, const int* __restrict__ dst) {
    int e = blockIdx.x * blockDim.x + threadIdx.x;
    if (e >= EPE) return;
    int s = src[e], d = dst[e];
    float nm = g_dinv[s] * g_dinv[d];
    const float4* xs = (const float4*)(g_x16 + s * 16);
    float4 a = xs[0], b = xs[1], c = xs[2], q = xs[3];
    float* yd = g_y + d * 16;
    red_add_v4(yd +  0, a.x * nm, a.y * nm, a.z * nm, a.w * nm);
    red_add_v4(yd +  4, b.x * nm, b.y * nm, b.z * nm, b.w * nm);
    red_add_v4(yd +  8, c.x * nm, c.y * nm, c.z * nm, c.w * nm);
    red_add_v4(yd + 12, q.x * nm, q.y * nm, q.z * nm, q.w * nm);  // q.w = 0
    atomicAdd(&g_c[s], nm);
}

// t[d] = sum_s c_s * relu(y[s]@Wp1[:,d] + bp1[d]); last block computes z_pocket/Apok
__global__ void k_hredzp(const float* __restrict__ Wp1, const float* __restrict__ bp1,
                         const float* __restrict__ Wp2, const float* __restrict__ bp2,
                         const float* __restrict__ Wh) {
    __shared__ float4 sy4[128 * 4];
    __shared__ float sc[128];
    __shared__ bool is_last;
    int n0 = blockIdx.x * 128;
    int nn = min(128, NPN - n0);
    int tid = threadIdx.x;
    float wc[16];
#pragma unroll
    for (int k = 0; k < 15; k++) wc[k] = Wp1[k * DD + tid];
    wc[15] = 0.f;
    float b = bp1[tid];
    for (int idx = tid; idx < nn * 4; idx += 256)
        sy4[idx] = ((const float4*)g_y)[n0 * 4 + idx];
    if (tid < nn) sc[tid] = g_c[n0 + tid];
    __syncthreads();
    float acc = 0.f;
    for (int j = 0; j < nn; j++) {
        float4 a = sy4[j*4+0], bb = sy4[j*4+1], c = sy4[j*4+2], q = sy4[j*4+3];
        float v = b;
        v += a.x*wc[0] + a.y*wc[1] + a.z*wc[2] + a.w*wc[3];
        v += bb.x*wc[4] + bb.y*wc[5] + bb.z*wc[6] + bb.w*wc[7];
        v += c.x*wc[8] + c.y*wc[9] + c.z*wc[10] + c.w*wc[11];
        v += q.x*wc[12] + q.y*wc[13] + q.z*wc[14];   // q.w is pad (0)
        acc += sc[j] * fmaxf(v, 0.f);
    }
    atomicAdd(&g_t[tid], acc);
    __threadfence();
    if (tid == 0) {
        unsigned int done = atomicAdd(&g_ctr, 1u);
        is_last = (done == gridDim.x - 1);
    }
    __syncthreads();
    if (!is_last) return;
    // ---- last block: z_pocket = bp2 + (1/N) t@Wp2 ; Apok_j = z_pocket . Wh[1:257, j]
    __shared__ float st[DD];
    __shared__ float szp[DD];
    st[tid] = __ldcg(&g_t[tid]);     // L1-bypass read of the reduced values
    __syncthreads();
    g_t[tid] = 0.f;                  // self-clean for next replay
    if (tid == 0) g_ctr = 0u;
    float acc2 = 0.f;
    for (int k = 0; k < DD; k++) acc2 += st[k] * Wp2[k * DD + tid];
    szp[tid] = bp2[tid] + acc2 * (1.f / (float)NPN);
    __syncthreads();
    int w = tid >> 5, lane = tid & 31;
    if (w < 4) {
        float p = 0.f;
        for (int d = lane; d < DD; d += 32) p += szp[d] * Wh[(1 + d) * 4 + w];
        for (int o = 16; o; o >>= 1) p += __shfl_xor_sync(0xffffffffu, p, o);
        if (lane == 0) g_Apok[w] = p;
    }
}

// ---------------- chain B: ligand / wd2p(single block, coalesced) / sim ----------------
__global__ void k_smallB(const float* __restrict__ Wh,
                         const float* __restrict__ xg, const int* __restrict__ xlab,
                         const int* __restrict__ srcl, const int* __restrict__ dstl,
                         const float* __restrict__ Wl1, const float* __restrict__ bl1,
                         const float* __restrict__ Wl2, const float* __restrict__ bl2,
                         const float* __restrict__ Wg, const float* __restrict__ bh,
                         const float* __restrict__ Wd2, const float* __restrict__ bd2,
                         const int* __restrict__ bfsi, const int* __restrict__ bfsb) {
    int blk = blockIdx.x;
    int tid = threadIdx.x;
    if (blk == 0) {
        // ligand GCN mean + constants
        __shared__ float xl[NLIG * 15];
        __shared__ float yl[NLIG * 15];
        __shared__ float dinv[NLIG], cl[NLIG], tl[DD], mz[DD];
        __shared__ int deg[NLIG], lab[NLIG];
        for (int i = tid; i < NLIG * 15; i += 256) xl[i] = 0.f;
        if (tid < NLIG) { deg[tid] = 0; lab[tid] = xlab[tid]; }
        __syncthreads();
        if (tid < NLIG) {
            for (int k = 0; k < 4; k++) xl[tid * 15 + k] = xg[tid * 4 + k];
            xl[tid * 15 + 4 + lab[tid]] = 1.f;
        }
        __syncthreads();
        if (tid < ELIG) atomicAdd(&deg[dstl[tid]], 1);
        __syncthreads();
        if (tid < NLIG) {
            float di = rsqrtf((float)(deg[tid] + 1));
            dinv[tid] = di;
            cl[tid] = di * di;
            for (int k = 0; k < 15; k++) yl[tid * 15 + k] = xl[tid * 15 + k] * di * di;
        }
        __syncthreads();
        if (tid < ELIG) {
            int s = srcl[tid], d = dstl[tid];
            float nm = dinv[s] * dinv[d];
            for (int k = 0; k < 15; k++) atomicAdd(&yl[d * 15 + k], xl[s * 15 + k] * nm);
            atomicAdd(&cl[s], nm);
        }
        __syncthreads();
        {
            float acc = 0.f;
            float b = bl1[tid];
            for (int s = 0; s < NLIG; s++) {
                float v = b;
#pragma unroll
                for (int k = 0; k < 15; k++) v += yl[s * 15 + k] * Wl1[k * DD + tid];
                acc += cl[s] * fmaxf(v, 0.f);
            }
            tl[tid] = acc;
        }
        __syncthreads();
        {
            float acc = 0.f;
            for (int k = 0; k < DD; k++) acc += tl[k] * Wl2[k * DD + tid];
            mz[tid] = bl2[tid] + acc * (1.f / 48.f);
        }
        __syncthreads();
        if (tid < N1) {
            int l = (tid < NLIG) ? lab[tid] : 10;
            g_lab49[tid] = l;
            g_labg[tid] = Wg[780 + l];
        }
        int w = tid >> 5, lane = tid & 31;
        if (w < 4) {
            int j = w;
            float p = 0.f;
            for (int d = lane; d < DD; d += 32) p += mz[d] * Wh[(1058 + d) * 4 + j];
            for (int n = lane; n < N1; n += 32) {
                int l = (n < NLIG) ? lab[n] : 10;
                p += (1.f / 49.f) * Wh[(1047 + l) * 4 + j];
            }
            for (int n = lane; n < NLIG; n += 32)
                p += (1.f / 48.f) * Wh[(1314 + lab[n]) * 4 + j];
            for (int o = 16; o; o >>= 1) p += __shfl_xor_sync(0xffffffffu, p, o);
            if (lane == 0) g_CONST[j] = p + bh[j];
        }
    } else if (blk == 1) {
        // Wd2P = Wd2 @ P, single block, coalesced via smem transpose tiles
        __shared__ float sP[DD * 13];        // P[kk][c]
        __shared__ float tile[16 * 257];     // transposed Wd2 chunk: [j][r]
        for (int idx = tid; idx < DD * 13; idx += 256) {
            int kk = idx / 13, c = idx - kk * 13;
            float p;
            if (c == 0)       p = Wg[524 + kk];
            else if (c < 5)   p = Wh[(257 + kk) * 4 + (c - 1)];
            else if (c < 9)   p = Wh[(524 + kk) * 4 + (c - 5)];
            else              p = Wh[(791 + kk) * 4 + (c - 9)];
            sP[idx] = p;
        }
        __syncthreads();
        float acc[13];
#pragma unroll
        for (int c = 0; c < 13; c++) acc[c] = 0.f;
        for (int kk0 = 0; kk0 < DD; kk0 += 16) {
            for (int q = tid; q < 1024; q += 256) {
                int r = q >> 2, j4 = q & 3;
                float4 v = *(const float4*)(Wd2 + r * DD + kk0 + j4 * 4);
                tile[(j4 * 4 + 0) * 257 + r] = v.x;
                tile[(j4 * 4 + 1) * 257 + r] = v.y;
                tile[(j4 * 4 + 2) * 257 + r] = v.z;
                tile[(j4 * 4 + 3) * 257 + r] = v.w;
            }
            __syncthreads();
#pragma unroll
            for (int j = 0; j < 16; j++) {
                float w = tile[j * 257 + tid];
                const float* p = &sP[(kk0 + j) * 13];
#pragma unroll
                for (int c = 0; c < 13; c++) acc[c] += w * p[c];
            }
            __syncthreads();
        }
#pragma unroll
        for (int c = 0; c < 13; c++) g_Wd2P[tid * 13 + c] = acc[c];
        if (tid < 13) {
            float s = 0.f;
            for (int kk = 0; kk < DD; kk++) s += bd2[kk] * sP[kk * 13 + tid];
            g_bd2P[tid] = s;
        }
    } else {
        // serial teacher-forced control simulation, smem-staged
        __shared__ int sbi[TSTEP * 2];
        __shared__ int sbb[TSTEP];
        __shared__ int slabs[N1];
        __shared__ int s_su[TSTEP], s_sv[TSTEP], s_sb[TSTEP], s_sstate[TSTEP];
        __shared__ unsigned char s_act[TSTEP], s_do[TSTEP];
        __shared__ float s_time[TSTEP];
        __shared__ unsigned long long s_mask[TSTEP];
        __shared__ float s_e[TSTEP * 4];
        __shared__ int s_src[193], s_dst[193];
        if (tid < TSTEP * 2) sbi[tid] = bfsi[tid];
        if (tid < TSTEP) sbb[tid] = bfsb[tid];
        if (tid < N1) slabs[tid] = (tid < NLIG) ? xlab[tid] : 10;
        if (tid < 193) { s_src[tid] = 0; s_dst[tid] = 0; }
        __syncthreads();
        if (tid == 0) {
            const float VALV[11] = {4.f,1.f,3.f,1.f,2.f,1.f,5.f,1.f,6.f,1.f,1000.f};
            const float BV[4] = {1.f,2.f,3.f,1.5f};
            const unsigned long long ALL49 = (1ull << 49) - 1ull;
            float val[N1];
            unsigned long long adj[N1];
            unsigned long long lowm = 0ull, closedm = 0ull;
            int Q[97];
            for (int i = 0; i < N1; i++) {
                val[i] = VALV[slabs[i]];
                adj[i] = 0ull;
                if (val[i] < 1.f) lowm |= (1ull << i);
            }
            int head = 0, tail = 1;
            Q[0] = sbi[0];
            int ne = 0;
            float tf = 0.f;
            s_src[0] = sbi[0];
            s_dst[0] = sbi[1];
            for (int t = 0; t < TSTEP; t++) {
                int v = sbi[t * 2 + 1], b = sbb[t];
                int active = (tail > head) ? 1 : 0;
                s_act[t] = (unsigned char)active;
                s_sv[t] = v; s_sb[t] = b; s_sstate[t] = ne; s_time[t] = tf;
                if (!active) {
                    s_do[t] = 0; s_su[t] = 0; s_mask[t] = 0ull;
                    s_e[t*4] = s_e[t*4+1] = s_e[t*4+2] = s_e[t*4+3] = 0.f;
                    continue;
                }
                int u = Q[head];
                s_su[t] = u;
                bool ulow = ((lowm >> u) & 1ull) != 0ull;
                unsigned long long base = lowm | closedm | adj[u] | (1ull << u);
                unsigned long long mask = ulow ? ALL49 : base;
                mask &= ~((1ull << v) | (1ull << 48));
                s_mask[t] = mask;
                bool mnouv = ulow || (((base >> v) & 1ull) != 0ull);
                int doe = (v != 48);
                s_do[t] = (unsigned char)doe;
                if (doe) {
                    float mv = fminf(val[u], val[v]);
                    float e0 = 0.f, e1 = 0.f, e2 = 0.f, e3 = 0.f;
                    if (mv <= 2.f) { e2 = NEGC; }
                    if (mv <= 1.f) { e0 = 0.f; e1 = NEGC; e2 = NEGC; e3 = 0.f; }
                    if (mv <= 0.f) { e0 = NEGC; e1 = NEGC; e2 = NEGC; e3 = NEGC; }
                    if (mnouv)     { e0 = NEGC; e1 = NEGC; e2 = NEGC; e3 = NEGC; }
                    if (b == 0) e0 = 0.f; else if (b == 1) e1 = 0.f;
                    else if (b == 2) e2 = 0.f; else e3 = 0.f;
                    s_e[t*4] = e0; s_e[t*4+1] = e1; s_e[t*4+2] = e2; s_e[t*4+3] = e3;
                    if (tail < 97) Q[tail] = v;
                    tail++;
                    ne++;
                    s_src[2*ne-1] = u; s_dst[2*ne-1] = v;
                    s_src[2*ne]   = v; s_dst[2*ne]   = u;
                    float dec = BV[b];
                    val[u] -= dec;
                    val[v] -= dec;
                    if (val[u] < 1.f) lowm |= (1ull << u); else lowm &= ~(1ull << u);
                    if (val[v] < 1.f) lowm |= (1ull << v); else lowm &= ~(1ull << v);
                    adj[u] |= (1ull << v);
                    adj[v] |= (1ull << u);
                    tf += 1.f;
                } else {
                    closedm |= (1ull << u);
                    head++;
                    s_e[t*4] = s_e[t*4+1] = s_e[t*4+2] = s_e[t*4+3] = 0.f;
                }
            }
            g_nedges = ne;
        }
        __syncthreads();
        if (tid < TSTEP) {
            g_su[tid] = s_su[tid]; g_sv[tid] = s_sv[tid];
            g_sb[tid] = s_sb[tid]; g_sstate[tid] = s_sstate[tid];
            g_sact[tid] = s_act[tid]; g_sdo[tid] = s_do[tid];
            g_stime[tid] = s_time[tid]; g_smask[tid] = s_mask[tid];
        }
        if (tid < TSTEP * 2) {
            g_se[tid] = s_e[tid];
            g_se[tid + TSTEP * 2] = s_e[tid + TSTEP * 2];
        }
        if (tid < 193) { g_dsrc[tid] = s_src[tid]; g_ddst[tid] = s_dst[tid]; }
    }
}

// ---------------- per-state inner GCN, projected to 13 dims ----------------
#define SMEM_STATES_FLOATS (N1*DD + 637 + 637 + 192 + N1 + 11*DD + 13*DD + N1 + 192 + 192 + N1)
#define SMEM_STATES_BYTES  (SMEM_STATES_FLOATS * 4)

__global__ void k_states(const float* __restrict__ Wd1, const float* __restrict__ bd1) {
    extern __shared__ float sm[];
    float* sh    = sm;                    // 49*256
    float* sg    = sh + N1 * DD;          // 637
    float* sz    = sg + 637;              // 637
    float* wE    = sz + 637;              // 192
    float* sdinv = wE + 192;              // 49
    float* sWd1  = sdinv + N1;            // 11*256
    float* sW2   = sWd1 + 11 * DD;        // 13*256 (layout: d*13+c)
    int* slab = (int*)(sW2 + 13 * DD);    // 49
    int* ses  = slab + N1;                // 192
    int* sed  = ses + 192;                // 192
    int* sdeg = sed + 192;                // 49
    int k = blockIdx.x;
    int K = g_nedges;
    if (k > K) return;
    int tid = threadIdx.x;
    int off = (k == 0) ? 0 : 1;
    int cnt = (k == 0) ? 1 : 2 * k;
    if (tid < N1) { slab[tid] = g_lab49[tid]; sdeg[tid] = 0; }
    if (tid < cnt) { ses[tid] = g_dsrc[off + tid]; sed[tid] = g_ddst[off + tid]; }
    for (int i = tid; i < 11 * DD; i += 256) sWd1[i] = Wd1[i];
    for (int i = tid; i < 13 * DD; i += 256) sW2[i] = g_Wd2P[i];
    __syncthreads();
    if (tid < cnt) atomicAdd(&sdeg[sed[tid]], 1);
    __syncthreads();
    if (tid < N1) sdinv[tid] = rsqrtf((float)(sdeg[tid] + 1));
    __syncthreads();
    if (tid < cnt) wE[tid] = sdinv[ses[tid]] * sdinv[sed[tid]];
    __syncthreads();
    // layer 1 : h = relu(bd1 + self + scatter(Wd1[lab[src]] * norm))
    // column d owned EXCLUSIVELY by thread d -> plain RMW, no atomics needed
    {
        int d = tid;
        float bd = bd1[d];
        for (int i = 0; i < N1; i++)
            sh[i * DD + d] = bd + sWd1[slab[i] * DD + d] * sdinv[i] * sdinv[i];
        for (int e = 0; e < cnt; e++)
            sh[sed[e] * DD + d] += sWd1[slab[ses[e]] * DD + d] * wE[e];
        for (int i = 0; i < N1; i++)
            sh[i * DD + d] = fmaxf(sh[i * DD + d], 0.f);
    }
    __syncthreads();
    // layer 2 projected: sg[i,c] = h[i] @ Wd2P[:,c]  (serial dot, no shuffles)
    for (int idx = tid; idx < 637; idx += 256) {
        int i = idx / 13, c = idx - i * 13;
        const float* hrow = sh + i * DD;
        float acc = 0.f;
#pragma unroll 4
        for (int d = 0; d < DD; d++)
            acc += hrow[d] * sW2[d * 13 + c];
        sg[idx] = acc;
    }
    __syncthreads();
    // self term + bias for ALL 637 entries
    for (int idx = tid; idx < 637; idx += 256) {
        int i = idx / 13, c = idx - i * 13;
        sz[idx] = g_bd2P[c] + sg[idx] * sdinv[i] * sdinv[i];
    }
    __syncthreads();
    // edge scatter of projections, parallel over (e, c) with smem atomics
    for (int idx = tid; idx < cnt * 13; idx += 256) {
        int e = idx / 13, c = idx - e * 13;
        atomicAdd(&sz[sed[e] * 13 + c], sg[ses[e] * 13 + c] * wE[e]);
    }
    __syncthreads();
    for (int idx = tid; idx < 637; idx += 256)
        g_zP[k * N1 * 13 + idx] = sz[idx];
    if (tid < 13) {
        float s = 0.f;
        for (int i = 0; i < N1; i++) s += sz[i * 13 + tid];
        g_mzP[k * 13 + tid] = s * (1.f / 49.f);
    }
}

// ---------------- final assembly of logp ----------------
__global__ void k_assemble(const float* __restrict__ Wh, float* __restrict__ out) {
    __shared__ float wsum[8];
    int tid = threadIdx.x, w = tid >> 5, lane = tid & 31;
    float acc = 0.f;
    for (int t = w; t < TSTEP; t += 8) {
        if (!g_sact[t]) continue;
        int st = g_sstate[t], v = g_sv[t], u = g_su[t], b = g_sb[t];
        unsigned long long mask = g_smask[t];
        const float* zPs = g_zP + st * N1 * 13;
        // glog softmax over 49 of zP[:,0] + labg + m
        int i0 = lane, i1 = lane + 32;
        float s0 = zPs[i0 * 13] + g_labg[i0] + (((mask >> i0) & 1ull) ? NEGC : 0.f);
        float s1 = (i1 < N1)
                 ? (zPs[i1 * 13] + g_labg[i1] + (((mask >> i1) & 1ull) ? NEGC : 0.f))
                 : -3.0e38f;
        float mx = fmaxf(s0, s1);
        for (int o = 16; o; o >>= 1) mx = fmaxf(mx, __shfl_xor_sync(0xffffffffu, mx, o));
        float se = expf(s0 - mx) + ((i1 < N1) ? expf(s1 - mx) : 0.f);
        for (int o = 16; o; o >>= 1) se += __shfl_xor_sync(0xffffffffu, se, o);
        float sgv = zPs[v * 13] + g_labg[v];     // m[v] == 0 always
        acc += sgv - (mx + logf(se));
        if (g_sdo[t]) {
            int j = lane & 3;
            int lu = g_lab49[u], lv = g_lab49[v];
            float h = g_stime[t] * Wh[j] + g_Apok[j]
                    + zPs[u * 13 + 1 + j] + Wh[(513 + lu) * 4 + j]
                    + zPs[v * 13 + 5 + j] + Wh[(780 + lv) * 4 + j]
                    + g_mzP[st * 13 + 9 + j] + g_CONST[j] + g_se[t * 4 + j];
            float m4 = h;
            m4 = fmaxf(m4, __shfl_xor_sync(0xffffffffu, m4, 1, 4));
            m4 = fmaxf(m4, __shfl_xor_sync(0xffffffffu, m4, 2, 4));
            float s4 = expf(h - m4);
            s4 += __shfl_xor_sync(0xffffffffu, s4, 1, 4);
            s4 += __shfl_xor_sync(0xffffffffu, s4, 2, 4);
            float hb = __shfl_sync(0xffffffffu, h, b, 4);
            acc += hb - (m4 + logf(s4));
        }
    }
    if (lane == 0) wsum[w] = acc;
    __syncthreads();
    if (tid == 0) {
        float s = 0.f;
        for (int i = 0; i < 8; i++) s += wsum[i];
        out[0] = s;
    }
}

// ---------------- launcher (fork-join: pocket chain || ligand/sim/states) ----------------
extern "C" void kernel_launch(void* const* d_in, const int* in_sizes, int n_in,
                              void* d_out, int out_size) {
    (void)in_sizes; (void)n_in; (void)out_size;
    const float* x_p   = (const float*)d_in[0];
    const int*   src_p = (const int*)d_in[1];
    const int*   dst_p = (const int*)d_in[2];
    const float* x_lg  = (const float*)d_in[3];
    const int*   x_ll  = (const int*)d_in[4];
    const int*   src_l = (const int*)d_in[5];
    const int*   dst_l = (const int*)d_in[6];
    const int*   bfsi  = (const int*)d_in[7];
    const int*   bfsb  = (const int*)d_in[8];
    const float* Wp1 = (const float*)d_in[9];
    const float* bp1 = (const float*)d_in[10];
    const float* Wp2 = (const float*)d_in[11];
    const float* bp2 = (const float*)d_in[12];
    const float* Wl1 = (const float*)d_in[13];
    const float* bl1 = (const float*)d_in[14];
    const float* Wl2 = (const float*)d_in[15];
    const float* bl2 = (const float*)d_in[16];
    const float* Wd1 = (const float*)d_in[17];
    const float* bd1 = (const float*)d_in[18];
    const float* Wd2 = (const float*)d_in[19];
    const float* bd2 = (const float*)d_in[20];
    // d_in[21] = Wf, d_in[22] = bf : dead code (logp reset by carry0)
    const float* Wg  = (const float*)d_in[23];
    // d_in[24] = bg : cancels under softmax shift-invariance
    const float* Wh  = (const float*)d_in[25];
    const float* bh  = (const float*)d_in[26];
    float* out = (float*)d_out;

    cudaFuncSetAttribute(k_states, cudaFuncAttributeMaxDynamicSharedMemorySize,
                         SMEM_STATES_BYTES);

    cudaStream_t sB;
    cudaEvent_t eFork, eJoin;
    cudaStreamCreateWithFlags(&sB, cudaStreamNonBlocking);
    cudaEventCreateWithFlags(&eFork, cudaEventDisableTiming);
    cudaEventCreateWithFlags(&eJoin, cudaEventDisableTiming);

    cudaEventRecord(eFork, 0);
    cudaStreamWaitEvent(sB, eFork, 0);

    // chain B (independent of pocket): ligand/wd2p/sim -> per-state GCN
    k_smallB<<<3, 256, 0, sB>>>(Wh, x_lg, x_ll, src_l, dst_l,
                                Wl1, bl1, Wl2, bl2, Wg, bh, Wd2, bd2, bfsi, bfsb);
    k_states<<<97, 256, SMEM_STATES_BYTES, sB>>>(Wd1, bd1);
    cudaEventRecord(eJoin, sB);

    // chain A (pocket GCN mean): deg -> dinv -> edge -> hred+zp (fused last-block)
    k_deg<<<(EPE + 255) / 256, 256>>>(dst_p);
    k_dinv<<<(NPN + 255) / 256, 256>>>(x_p);
    k_edge<<<(EPE + 255) / 256, 256>>>(src_p, dst_p);
    k_hredzp<<<(NPN + 127) / 128, 256>>>(Wp1, bp1, Wp2, bp2, Wh);

    // join and assemble
    cudaStreamWaitEvent(0, eJoin, 0);
    k_assemble<<<1, 256>>>(Wh, out);
}

// round 17
// speedup vs baseline: 2.2464x; 1.0440x over previous
#include <cuda_runtime.h>
#include <cuda_bf16.h>
#include <math.h>

#define NPN   30000
#define EPE   480000
#define NLIG  48
#define ELIG  144
#define TSTEP 96
#define N1    49
#define DD    256
#define NEGC  (-1.0e9f)

// ---------------- device scratch (static; no allocations) ----------------
__device__ int   g_deg[NPN];
__device__ float g_dinv[NPN];
__device__ __align__(16) float g_y[NPN * 16];    // padded to 16 floats/row
__device__ __align__(16) float g_x16[NPN * 16];  // raw x, padded for LDG.128
__device__ float g_c[NPN];
__device__ float g_t[DD];
__device__ unsigned int g_ctr;
__device__ float g_Apok[4];
__device__ float g_CONST[4];     // H_t lab part + H_init + bh
__device__ float g_labg[N1];     // Wg[780 + lab_i]
__device__ int   g_lab49[N1];
__device__ float g_Wd2P[DD * 13];
__device__ float g_bd2P[13];
// sim outputs
__device__ int   g_nedges;
__device__ int   g_dsrc[193], g_ddst[193];
__device__ int   g_su[TSTEP], g_sv[TSTEP], g_sb[TSTEP], g_sstate[TSTEP];
__device__ unsigned char g_sact[TSTEP], g_sdo[TSTEP];
__device__ float g_stime[TSTEP];
__device__ unsigned long long g_smask[TSTEP];
__device__ float g_se[TSTEP * 4];
// per-state projected GCN outputs
__device__ float g_zP[97 * N1 * 13];
__device__ float g_mzP[97 * 13];

__device__ __forceinline__ void red_add_v4(float* p, float a, float b, float c, float d) {
    asm volatile("red.global.add.v4.f32 [%0], {%1, %2, %3, %4};"
                 :: "l"(p), "f"(a), "f"(b), "f"(c), "f"(d) : "memory");
}

// ---------------- pocket GCN (mean only) ----------------
__global__ void k_deg(const int* __restrict__ dst) {
    int e = blockIdx.x * blockDim.x + threadIdx.x;
    if (e < EPE) atomicAdd(&g_deg[dst[e]], 1);
}

__global__ void k_dinv(const float* __restrict__ xp) {
    int i = blockIdx.x * blockDim.x + threadIdx.x;
    if (i >= NPN) return;
    float di = rsqrtf((float)(g_deg[i] + 1));
    g_deg[i] = 0;                     // self-clean for next graph replay
    g_dinv[i] = di;
    float w = di * di;
    g_c[i] = w;                       // self-loop contribution to c_s
    const float* xr = xp + i * 15;
    float x[16];
#pragma unroll
    for (int k = 0; k < 15; k++) x[k] = xr[k];
    x[15] = 0.f;
    float4* xw = (float4*)(g_x16 + i * 16);
    float4* yr = (float4*)(g_y + i * 16);
#pragma unroll
    for (int q = 0; q < 4; q++) {
        float4 xv = make_float4(x[q*4], x[q*4+1], x[q*4+2], x[q*4+3]);
        xw[q] = xv;
        yr[q] = make_float4(xv.x * w, xv.y * w, xv.z * w, xv.w * w);
    }
}

// 4x LDG.128 gather + 4x RED.v4 scatter per edge (issue-floor optimized)
__global__ void k_edge(const int* __restrict__ src, const int* __restrict__ dst) {
    int e = blockIdx.x * blockDim.x + threadIdx.x;
    if (e >= EPE) return;
    int s = src[e], d = dst[e];
    float nm = g_dinv[s] * g_dinv[d];
    const float4* xs = (const float4*)(g_x16 + s * 16);
    float4 a = xs[0], b = xs[1], c = xs[2], q = xs[3];
    float* yd = g_y + d * 16;
    red_add_v4(yd +  0, a.x * nm, a.y * nm, a.z * nm, a.w * nm);
    red_add_v4(yd +  4, b.x * nm, b.y * nm, b.z * nm, b.w * nm);
    red_add_v4(yd +  8, c.x * nm, c.y * nm, c.z * nm, c.w * nm);
    red_add_v4(yd + 12, q.x * nm, q.y * nm, q.z * nm, q.w * nm);  // q.w = 0
    atomicAdd(&g_c[s], nm);
}

// t[d] = sum_s c_s * relu(y[s]@Wp1[:,d] + bp1[d]); last block computes z_pocket/Apok
__global__ void k_hredzp(const float* __restrict__ Wp1, const float* __restrict__ bp1,
                         const float* __restrict__ Wp2, const float* __restrict__ bp2,
                         const float* __restrict__ Wh) {
    __shared__ float4 sy4[128 * 4];
    __shared__ float sc[128];
    __shared__ bool is_last;
    int n0 = blockIdx.x * 128;
    int nn = min(128, NPN - n0);
    int tid = threadIdx.x;
    float wc[16];
#pragma unroll
    for (int k = 0; k < 15; k++) wc[k] = Wp1[k * DD + tid];
    wc[15] = 0.f;
    float b = bp1[tid];
    for (int idx = tid; idx < nn * 4; idx += 256)
        sy4[idx] = ((const float4*)g_y)[n0 * 4 + idx];
    if (tid < nn) sc[tid] = g_c[n0 + tid];
    __syncthreads();
    float acc = 0.f;
    for (int j = 0; j < nn; j++) {
        float4 a = sy4[j*4+0], bb = sy4[j*4+1], c = sy4[j*4+2], q = sy4[j*4+3];
        float v = b;
        v += a.x*wc[0] + a.y*wc[1] + a.z*wc[2] + a.w*wc[3];
        v += bb.x*wc[4] + bb.y*wc[5] + bb.z*wc[6] + bb.w*wc[7];
        v += c.x*wc[8] + c.y*wc[9] + c.z*wc[10] + c.w*wc[11];
        v += q.x*wc[12] + q.y*wc[13] + q.z*wc[14];   // q.w is pad (0)
        acc += sc[j] * fmaxf(v, 0.f);
    }
    atomicAdd(&g_t[tid], acc);
    __threadfence();
    __syncthreads();   // all warps' g_t atomics issued+fenced before counter bump
    if (tid == 0) {
        unsigned int done = atomicAdd(&g_ctr, 1u);
        is_last = (done == gridDim.x - 1);
    }
    __syncthreads();
    if (!is_last) return;
    // ---- last block: z_pocket = bp2 + (1/N) t@Wp2 ; Apok_j = z_pocket . Wh[1:257, j]
    __shared__ float st[DD];
    __shared__ float szp[DD];
    st[tid] = __ldcg(&g_t[tid]);     // L1-bypass read of the reduced values
    __syncthreads();
    g_t[tid] = 0.f;                  // self-clean for next replay
    if (tid == 0) g_ctr = 0u;
    float acc2 = 0.f;
    for (int k = 0; k < DD; k++) acc2 += st[k] * Wp2[k * DD + tid];
    szp[tid] = bp2[tid] + acc2 * (1.f / (float)NPN);
    __syncthreads();
    int w = tid >> 5, lane = tid & 31;
    if (w < 4) {
        float p = 0.f;
        for (int d = lane; d < DD; d += 32) p += szp[d] * Wh[(1 + d) * 4 + w];
        for (int o = 16; o; o >>= 1) p += __shfl_xor_sync(0xffffffffu, p, o);
        if (lane == 0) g_Apok[w] = p;
    }
}

// ---------------- chain B: ligand / wd2p(single block, coalesced) / sim ----------------
__global__ void k_smallB(const float* __restrict__ Wh,
                         const float* __restrict__ xg, const int* __restrict__ xlab,
                         const int* __restrict__ srcl, const int* __restrict__ dstl,
                         const float* __restrict__ Wl1, const float* __restrict__ bl1,
                         const float* __restrict__ Wl2, const float* __restrict__ bl2,
                         const float* __restrict__ Wg, const float* __restrict__ bh,
                         const float* __restrict__ Wd2, const float* __restrict__ bd2,
                         const int* __restrict__ bfsi, const int* __restrict__ bfsb) {
    int blk = blockIdx.x;
    int tid = threadIdx.x;
    if (blk == 0) {
        // ligand GCN mean + constants
        __shared__ float xl[NLIG * 15];
        __shared__ float yl[NLIG * 15];
        __shared__ float dinv[NLIG], cl[NLIG], tl[DD], mz[DD];
        __shared__ int deg[NLIG], lab[NLIG];
        for (int i = tid; i < NLIG * 15; i += 256) xl[i] = 0.f;
        if (tid < NLIG) { deg[tid] = 0; lab[tid] = xlab[tid]; }
        __syncthreads();
        if (tid < NLIG) {
            for (int k = 0; k < 4; k++) xl[tid * 15 + k] = xg[tid * 4 + k];
            xl[tid * 15 + 4 + lab[tid]] = 1.f;
        }
        __syncthreads();
        if (tid < ELIG) atomicAdd(&deg[dstl[tid]], 1);
        __syncthreads();
        if (tid < NLIG) {
            float di = rsqrtf((float)(deg[tid] + 1));
            dinv[tid] = di;
            cl[tid] = di * di;
            for (int k = 0; k < 15; k++) yl[tid * 15 + k] = xl[tid * 15 + k] * di * di;
        }
        __syncthreads();
        if (tid < ELIG) {
            int s = srcl[tid], d = dstl[tid];
            float nm = dinv[s] * dinv[d];
            for (int k = 0; k < 15; k++) atomicAdd(&yl[d * 15 + k], xl[s * 15 + k] * nm);
            atomicAdd(&cl[s], nm);
        }
        __syncthreads();
        {
            float acc = 0.f;
            float b = bl1[tid];
            for (int s = 0; s < NLIG; s++) {
                float v = b;
#pragma unroll
                for (int k = 0; k < 15; k++) v += yl[s * 15 + k] * Wl1[k * DD + tid];
                acc += cl[s] * fmaxf(v, 0.f);
            }
            tl[tid] = acc;
        }
        __syncthreads();
        {
            float acc = 0.f;
            for (int k = 0; k < DD; k++) acc += tl[k] * Wl2[k * DD + tid];
            mz[tid] = bl2[tid] + acc * (1.f / 48.f);
        }
        __syncthreads();
        if (tid < N1) {
            int l = (tid < NLIG) ? lab[tid] : 10;
            g_lab49[tid] = l;
            g_labg[tid] = Wg[780 + l];
        }
        int w = tid >> 5, lane = tid & 31;
        if (w < 4) {
            int j = w;
            float p = 0.f;
            for (int d = lane; d < DD; d += 32) p += mz[d] * Wh[(1058 + d) * 4 + j];
            for (int n = lane; n < N1; n += 32) {
                int l = (n < NLIG) ? lab[n] : 10;
                p += (1.f / 49.f) * Wh[(1047 + l) * 4 + j];
            }
            for (int n = lane; n < NLIG; n += 32)
                p += (1.f / 48.f) * Wh[(1314 + lab[n]) * 4 + j];
            for (int o = 16; o; o >>= 1) p += __shfl_xor_sync(0xffffffffu, p, o);
            if (lane == 0) g_CONST[j] = p + bh[j];
        }
    } else if (blk == 1) {
        // Wd2P = Wd2 @ P, single block, coalesced via smem transpose tiles (8-wide)
        __shared__ float sP[DD * 13];        // P[kk][c]
        __shared__ float tile[8 * 257];      // transposed Wd2 chunk: [j][r]
        for (int idx = tid; idx < DD * 13; idx += 256) {
            int kk = idx / 13, c = idx - kk * 13;
            float p;
            if (c == 0)       p = Wg[524 + kk];
            else if (c < 5)   p = Wh[(257 + kk) * 4 + (c - 1)];
            else if (c < 9)   p = Wh[(524 + kk) * 4 + (c - 5)];
            else              p = Wh[(791 + kk) * 4 + (c - 9)];
            sP[idx] = p;
        }
        __syncthreads();
        float acc[13];
#pragma unroll
        for (int c = 0; c < 13; c++) acc[c] = 0.f;
        for (int kk0 = 0; kk0 < DD; kk0 += 8) {
            for (int q = tid; q < 512; q += 256) {       // 512 float4 = 2048 floats
                int r = q >> 1, j4 = q & 1;
                float4 v = *(const float4*)(Wd2 + r * DD + kk0 + j4 * 4);
                tile[(j4 * 4 + 0) * 257 + r] = v.x;
                tile[(j4 * 4 + 1) * 257 + r] = v.y;
                tile[(j4 * 4 + 2) * 257 + r] = v.z;
                tile[(j4 * 4 + 3) * 257 + r] = v.w;
            }
            __syncthreads();
#pragma unroll
            for (int j = 0; j < 8; j++) {
                float w = tile[j * 257 + tid];
                const float* p = &sP[(kk0 + j) * 13];
#pragma unroll
                for (int c = 0; c < 13; c++) acc[c] += w * p[c];
            }
            __syncthreads();
        }
#pragma unroll
        for (int c = 0; c < 13; c++) g_Wd2P[tid * 13 + c] = acc[c];
        if (tid < 13) {
            float s = 0.f;
            for (int kk = 0; kk < DD; kk++) s += bd2[kk] * sP[kk * 13 + tid];
            g_bd2P[tid] = s;
        }
    } else {
        // serial teacher-forced control simulation; mutable state in SMEM
        __shared__ int sbi[TSTEP * 2];
        __shared__ int sbb[TSTEP];
        __shared__ int slabs[N1];
        __shared__ float s_VALV[11];
        __shared__ float s_BV[4];
        __shared__ float s_val[N1];
        __shared__ unsigned long long s_adjm[N1];
        __shared__ int s_Qq[97];
        __shared__ int s_su[TSTEP], s_sv[TSTEP], s_sb[TSTEP], s_sstate[TSTEP];
        __shared__ unsigned char s_act[TSTEP], s_do[TSTEP];
        __shared__ float s_time[TSTEP];
        __shared__ unsigned long long s_mask[TSTEP];
        __shared__ float s_e[TSTEP * 4];
        __shared__ int s_src[193], s_dst[193];
        if (tid < TSTEP * 2) sbi[tid] = bfsi[tid];
        if (tid < TSTEP) sbb[tid] = bfsb[tid];
        if (tid < N1) slabs[tid] = (tid < NLIG) ? xlab[tid] : 10;
        if (tid < 193) { s_src[tid] = 0; s_dst[tid] = 0; }
        if (tid < 11) {
            const float VALVc[11] = {4.f,1.f,3.f,1.f,2.f,1.f,5.f,1.f,6.f,1.f,1000.f};
            s_VALV[tid] = VALVc[tid];
        }
        if (tid < 4) {
            const float BVc[4] = {1.f,2.f,3.f,1.5f};
            s_BV[tid] = BVc[tid];
        }
        __syncthreads();
        // parallel state init (VALV entries are all >= 1 -> initial lowm == 0)
        if (tid < N1) {
            s_val[tid] = s_VALV[slabs[tid]];
            s_adjm[tid] = 0ull;
        }
        __syncthreads();
        if (tid == 0) {
            const unsigned long long ALL49 = (1ull << 49) - 1ull;
            unsigned long long lowm = 0ull, closedm = 0ull;
            int head = 0, tail = 1;
            s_Qq[0] = sbi[0];
            int ne = 0;
            float tf = 0.f;
            s_src[0] = sbi[0];
            s_dst[0] = sbi[1];
            for (int t = 0; t < TSTEP; t++) {
                int v = sbi[t * 2 + 1], b = sbb[t];
                int active = (tail > head) ? 1 : 0;
                s_act[t] = (unsigned char)active;
                s_sv[t] = v; s_sb[t] = b; s_sstate[t] = ne; s_time[t] = tf;
                if (!active) {
                    s_do[t] = 0; s_su[t] = 0; s_mask[t] = 0ull;
                    s_e[t*4] = s_e[t*4+1] = s_e[t*4+2] = s_e[t*4+3] = 0.f;
                    continue;
                }
                int u = s_Qq[head];
                s_su[t] = u;
                bool ulow = ((lowm >> u) & 1ull) != 0ull;
                unsigned long long base = lowm | closedm | s_adjm[u] | (1ull << u);
                unsigned long long mask = ulow ? ALL49 : base;
                mask &= ~((1ull << v) | (1ull << 48));
                s_mask[t] = mask;
                bool mnouv = ulow || (((base >> v) & 1ull) != 0ull);
                int doe = (v != 48);
                s_do[t] = (unsigned char)doe;
                if (doe) {
                    float mv = fminf(s_val[u], s_val[v]);
                    float e0 = 0.f, e1 = 0.f, e2 = 0.f, e3 = 0.f;
                    if (mv <= 2.f) { e2 = NEGC; }
                    if (mv <= 1.f) { e0 = 0.f; e1 = NEGC; e2 = NEGC; e3 = 0.f; }
                    if (mv <= 0.f) { e0 = NEGC; e1 = NEGC; e2 = NEGC; e3 = NEGC; }
                    if (mnouv)     { e0 = NEGC; e1 = NEGC; e2 = NEGC; e3 = NEGC; }
                    if (b == 0) e0 = 0.f; else if (b == 1) e1 = 0.f;
                    else if (b == 2) e2 = 0.f; else e3 = 0.f;
                    s_e[t*4] = e0; s_e[t*4+1] = e1; s_e[t*4+2] = e2; s_e[t*4+3] = e3;
                    if (tail < 97) s_Qq[tail] = v;
                    tail++;
                    ne++;
                    s_src[2*ne-1] = u; s_dst[2*ne-1] = v;
                    s_src[2*ne]   = v; s_dst[2*ne]   = u;
                    float dec = s_BV[b];
                    // ALIAS FIX (u may equal v): sequential RMWs, exactly like
                    // the reference's val.at[u].add(-dec).at[v].add(-dec).
                    float vu = s_val[u] - dec;
                    s_val[u] = vu;
                    float vv = s_val[v] - dec;   // re-reads; if v==u this is vu-dec
                    s_val[v] = vv;
                    // lowm from post-store values; for u==v the v-update (final
                    // value) overwrites the u-update on the same bit.
                    if (vu < 1.f) lowm |= (1ull << u); else lowm &= ~(1ull << u);
                    if (vv < 1.f) lowm |= (1ull << v); else lowm &= ~(1ull << v);
                    s_adjm[u] |= (1ull << v);
                    s_adjm[v] |= (1ull << u);
                    tf += 1.f;
                } else {
                    closedm |= (1ull << u);
                    head++;
                    s_e[t*4] = s_e[t*4+1] = s_e[t*4+2] = s_e[t*4+3] = 0.f;
                }
            }
            g_nedges = ne;
        }
        __syncthreads();
        if (tid < TSTEP) {
            g_su[tid] = s_su[tid]; g_sv[tid] = s_sv[tid];
            g_sb[tid] = s_sb[tid]; g_sstate[tid] = s_sstate[tid];
            g_sact[tid] = s_act[tid]; g_sdo[tid] = s_do[tid];
            g_stime[tid] = s_time[tid]; g_smask[tid] = s_mask[tid];
        }
        if (tid < TSTEP * 2) {
            g_se[tid] = s_e[tid];
            g_se[tid + TSTEP * 2] = s_e[tid + TSTEP * 2];
        }
        if (tid < 193) { g_dsrc[tid] = s_src[tid]; g_ddst[tid] = s_dst[tid]; }
    }
}

// ---------------- per-state inner GCN, projected to 13 dims ----------------
#define SMEM_STATES_FLOATS (N1*DD + 637 + 637 + 192 + N1 + 11*DD + 13*DD + N1 + 192 + 192 + N1)
#define SMEM_STATES_BYTES  (SMEM_STATES_FLOATS * 4)

__global__ void k_states(const float* __restrict__ Wd1, const float* __restrict__ bd1) {
    extern __shared__ float sm[];
    float* sh    = sm;                    // 49*256
    float* sg    = sh + N1 * DD;          // 637
    float* sz    = sg + 637;              // 637
    float* wE    = sz + 637;              // 192
    float* sdinv = wE + 192;              // 49
    float* sWd1  = sdinv + N1;            // 11*256
    float* sW2   = sWd1 + 11 * DD;        // 13*256 (layout: d*13+c)
    int* slab = (int*)(sW2 + 13 * DD);    // 49
    int* ses  = slab + N1;                // 192
    int* sed  = ses + 192;                // 192
    int* sdeg = sed + 192;                // 49
    int k = blockIdx.x;
    int K = g_nedges;
    if (k > K) return;
    int tid = threadIdx.x;
    int off = (k == 0) ? 0 : 1;
    int cnt = (k == 0) ? 1 : 2 * k;
    if (tid < N1) { slab[tid] = g_lab49[tid]; sdeg[tid] = 0; }
    if (tid < cnt) { ses[tid] = g_dsrc[off + tid]; sed[tid] = g_ddst[off + tid]; }
    for (int i = tid; i < 11 * DD; i += 256) sWd1[i] = Wd1[i];
    for (int i = tid; i < 13 * DD; i += 256) sW2[i] = g_Wd2P[i];
    __syncthreads();
    if (tid < cnt) atomicAdd(&sdeg[sed[tid]], 1);
    __syncthreads();
    if (tid < N1) sdinv[tid] = rsqrtf((float)(sdeg[tid] + 1));
    __syncthreads();
    if (tid < cnt) wE[tid] = sdinv[ses[tid]] * sdinv[sed[tid]];
    __syncthreads();
    // layer 1 : h = relu(bd1 + self + scatter(Wd1[lab[src]] * norm))
    // column d owned EXCLUSIVELY by thread d -> plain RMW, no atomics needed
    {
        int d = tid;
        float bd = bd1[d];
        for (int i = 0; i < N1; i++)
            sh[i * DD + d] = bd + sWd1[slab[i] * DD + d] * sdinv[i] * sdinv[i];
        for (int e = 0; e < cnt; e++)
            sh[sed[e] * DD + d] += sWd1[slab[ses[e]] * DD + d] * wE[e];
        for (int i = 0; i < N1; i++)
            sh[i * DD + d] = fmaxf(sh[i * DD + d], 0.f);
    }
    __syncthreads();
    // layer 2 projected: sg[i,c] = h[i] @ Wd2P[:,c]  (serial dot, no shuffles)
    for (int idx = tid; idx < 637; idx += 256) {
        int i = idx / 13, c = idx - i * 13;
        const float* hrow = sh + i * DD;
        float acc = 0.f;
#pragma unroll 4
        for (int d = 0; d < DD; d++)
            acc += hrow[d] * sW2[d * 13 + c];
        sg[idx] = acc;
    }
    __syncthreads();
    // self term + bias for ALL 637 entries
    for (int idx = tid; idx < 637; idx += 256) {
        int i = idx / 13, c = idx - i * 13;
        sz[idx] = g_bd2P[c] + sg[idx] * sdinv[i] * sdinv[i];
    }
    __syncthreads();
    // edge scatter of projections, parallel over (e, c) with smem atomics
    for (int idx = tid; idx < cnt * 13; idx += 256) {
        int e = idx / 13, c = idx - e * 13;
        atomicAdd(&sz[sed[e] * 13 + c], sg[ses[e] * 13 + c] * wE[e]);
    }
    __syncthreads();
    for (int idx = tid; idx < 637; idx += 256)
        g_zP[k * N1 * 13 + idx] = sz[idx];
    if (tid < 13) {
        float s = 0.f;
        for (int i = 0; i < N1; i++) s += sz[i * 13 + tid];
        g_mzP[k * 13 + tid] = s * (1.f / 49.f);
    }
}

// ---------------- final assembly of logp ----------------
__global__ void k_assemble(const float* __restrict__ Wh, float* __restrict__ out) {
    __shared__ float wsum[8];
    int tid = threadIdx.x, w = tid >> 5, lane = tid & 31;
    float acc = 0.f;
    for (int t = w; t < TSTEP; t += 8) {
        if (!g_sact[t]) continue;
        int st = g_sstate[t], v = g_sv[t], u = g_su[t], b = g_sb[t];
        unsigned long long mask = g_smask[t];
        const float* zPs = g_zP + st * N1 * 13;
        // glog softmax over 49 of zP[:,0] + labg + m
        int i0 = lane, i1 = lane + 32;
        float s0 = zPs[i0 * 13] + g_labg[i0] + (((mask >> i0) & 1ull) ? NEGC : 0.f);
        float s1 = (i1 < N1)
                 ? (zPs[i1 * 13] + g_labg[i1] + (((mask >> i1) & 1ull) ? NEGC : 0.f))
                 : -3.0e38f;
        float mx = fmaxf(s0, s1);
        for (int o = 16; o; o >>= 1) mx = fmaxf(mx, __shfl_xor_sync(0xffffffffu, mx, o));
        float se = expf(s0 - mx) + ((i1 < N1) ? expf(s1 - mx) : 0.f);
        for (int o = 16; o; o >>= 1) se += __shfl_xor_sync(0xffffffffu, se, o);
        float sgv = zPs[v * 13] + g_labg[v];     // m[v] == 0 always
        acc += sgv - (mx + logf(se));
        if (g_sdo[t]) {
            int j = lane & 3;
            int lu = g_lab49[u], lv = g_lab49[v];
            float h = g_stime[t] * Wh[j] + g_Apok[j]
                    + zPs[u * 13 + 1 + j] + Wh[(513 + lu) * 4 + j]
                    + zPs[v * 13 + 5 + j] + Wh[(780 + lv) * 4 + j]
                    + g_mzP[st * 13 + 9 + j] + g_CONST[j] + g_se[t * 4 + j];
            float m4 = h;
            m4 = fmaxf(m4, __shfl_xor_sync(0xffffffffu, m4, 1, 4));
            m4 = fmaxf(m4, __shfl_xor_sync(0xffffffffu, m4, 2, 4));
            float s4 = expf(h - m4);
            s4 += __shfl_xor_sync(0xffffffffu, s4, 1, 4);
            s4 += __shfl_xor_sync(0xffffffffu, s4, 2, 4);
            float hb = __shfl_sync(0xffffffffu, h, b, 4);
            acc += hb - (m4 + logf(s4));
        }
    }
    if (lane == 0) wsum[w] = acc;
    __syncthreads();
    if (tid == 0) {
        float s = 0.f;
        for (int i = 0; i < 8; i++) s += wsum[i];
        out[0] = s;
    }
}

// ---------------- launcher (fork-join: pocket chain || ligand/sim/states) ----------------
extern "C" void kernel_launch(void* const* d_in, const int* in_sizes, int n_in,
                              void* d_out, int out_size) {
    (void)in_sizes; (void)n_in; (void)out_size;
    const float* x_p   = (const float*)d_in[0];
    const int*   src_p = (const int*)d_in[1];
    const int*   dst_p = (const int*)d_in[2];
    const float* x_lg  = (const float*)d_in[3];
    const int*   x_ll  = (const int*)d_in[4];
    const int*   src_l = (const int*)d_in[5];
    const int*   dst_l = (const int*)d_in[6];
    const int*   bfsi  = (const int*)d_in[7];
    const int*   bfsb  = (const int*)d_in[8];
    const float* Wp1 = (const float*)d_in[9];
    const float* bp1 = (const float*)d_in[10];
    const float* Wp2 = (const float*)d_in[11];
    const float* bp2 = (const float*)d_in[12];
    const float* Wl1 = (const float*)d_in[13];
    const float* bl1 = (const float*)d_in[14];
    const float* Wl2 = (const float*)d_in[15];
    const float* bl2 = (const float*)d_in[16];
    const float* Wd1 = (const float*)d_in[17];
    const float* bd1 = (const float*)d_in[18];
    const float* Wd2 = (const float*)d_in[19];
    const float* bd2 = (const float*)d_in[20];
    // d_in[21] = Wf, d_in[22] = bf : dead code (logp reset by carry0)
    const float* Wg  = (const float*)d_in[23];
    // d_in[24] = bg : cancels under softmax shift-invariance
    const float* Wh  = (const float*)d_in[25];
    const float* bh  = (const float*)d_in[26];
    float* out = (float*)d_out;

    cudaFuncSetAttribute(k_states, cudaFuncAttributeMaxDynamicSharedMemorySize,
                         SMEM_STATES_BYTES);

    cudaStream_t sB;
    cudaEvent_t eFork, eJoin;
    cudaStreamCreateWithFlags(&sB, cudaStreamNonBlocking);
    cudaEventCreateWithFlags(&eFork, cudaEventDisableTiming);
    cudaEventCreateWithFlags(&eJoin, cudaEventDisableTiming);

    cudaEventRecord(eFork, 0);
    cudaStreamWaitEvent(sB, eFork, 0);

    // chain B (independent of pocket): ligand/wd2p/sim -> per-state GCN
    k_smallB<<<3, 256, 0, sB>>>(Wh, x_lg, x_ll, src_l, dst_l,
                                Wl1, bl1, Wl2, bl2, Wg, bh, Wd2, bd2, bfsi, bfsb);
    k_states<<<97, 256, SMEM_STATES_BYTES, sB>>>(Wd1, bd1);
    cudaEventRecord(eJoin, sB);

    // chain A (pocket GCN mean): deg -> dinv -> edge -> hred+zp (fused last-block)
    k_deg<<<(EPE + 255) / 256, 256>>>(dst_p);
    k_dinv<<<(NPN + 255) / 256, 256>>>(x_p);
    k_edge<<<(EPE + 255) / 256, 256>>>(src_p, dst_p);
    k_hredzp<<<(NPN + 127) / 128, 256>>>(Wp1, bp1, Wp2, bp2, Wh);

    // join and assemble
    cudaStreamWaitEvent(0, eJoin, 0);
    k_assemble<<<1, 256>>>(Wh, out);
}